// round 1
// baseline (speedup 1.0000x reference)
#include <cuda_runtime.h>
#include <cuda_bf16.h>
#include <cstdint>

// ---------------- problem constants ----------------
#define NB 16        // batch
#define NC 80        // classes
#define NP 17064     // total locations across 5 levels
#define PRE_K 1000
#define POST_K 100
#define IMG_W_F 1024.0f
#define IMG_H_F 800.0f
#define THRESH_F 0.05f
#define IOU_THR_F 0.6f
#define CLS_OFF_F 4096.0f

// level offsets: hw = 12800, 3200, 800, 208, 56
// offsets:        0, 12800, 16000, 16800, 17008

struct Ptrs {
    const float* cls[5];
    const float* reg[5];
    const float* ctr[5];
};

// ---------------- device scratch (static, no allocs) ----------------
__device__ float    g_scores[NB * NP];
__device__ int      g_labels[NB * NP];
__device__ float    g_boxes [NB * NP * 4];
__device__ unsigned g_pivot [NB];
__device__ int      g_gcnt  [NB];
__device__ unsigned g_cbits [NB * 1024];
__device__ int      g_cidx  [NB * 1024];
__device__ float    g_tscore[NB * PRE_K];
__device__ int      g_tlabel[NB * PRE_K];
__device__ float    g_tbox  [NB * PRE_K * 4];

__device__ __forceinline__ float sigmoidf_(float x) {
    return 1.0f / (1.0f + expf(-x));
}

// ============ Kernel 1: decode scores/labels/boxes per location ============
__global__ void k_decode(Ptrs p) {
    int gid = blockIdx.x * blockDim.x + threadIdx.x;
    if (gid >= NB * NP) return;
    int n = gid / NP;
    int loc = gid - n * NP;

    int l, off, ww, stride;
    if (loc < 12800)      { l = 0; off = 0;     ww = 128; stride = 8;   }
    else if (loc < 16000) { l = 1; off = 12800; ww = 64;  stride = 16;  }
    else if (loc < 16800) { l = 2; off = 16000; ww = 32;  stride = 32;  }
    else if (loc < 17008) { l = 3; off = 16800; ww = 16;  stride = 64;  }
    else                  { l = 4; off = 17008; ww = 8;   stride = 128; }

    int local = loc - off;
    int hw;
    switch (l) {
        case 0: hw = 12800; break;
        case 1: hw = 3200;  break;
        case 2: hw = 800;   break;
        case 3: hw = 208;   break;
        default: hw = 56;   break;
    }
    int y = local / ww;
    int x = local - y * ww;

    // argmax over class logits (sigmoid monotone => same argmax as scores)
    const float* cls = p.cls[l] + (size_t)n * NC * hw + local;
    float m = cls[0];
    int mi = 0;
#pragma unroll 4
    for (int c = 1; c < NC; c++) {
        float v = cls[(size_t)c * hw];
        if (v > m) { m = v; mi = c; }
    }
    float ctr = p.ctr[l][(size_t)n * hw + local];
    float s = sqrtf(sigmoidf_(m) * sigmoidf_(ctr));
    if (!(s > THRESH_F)) s = 0.0f;

    const float* reg = p.reg[l] + (size_t)n * 4 * hw + local;
    float dl = reg[0];
    float dt = reg[hw];
    float dr = reg[2 * hw];
    float db = reg[3 * hw];

    float px = (float)x * (float)stride + 0.5f * (float)stride;
    float py = (float)y * (float)stride + 0.5f * (float)stride;

    float x1 = fminf(fmaxf(px - dl, 0.0f), IMG_W_F);
    float y1 = fminf(fmaxf(py - dt, 0.0f), IMG_H_F);
    float x2 = fminf(fmaxf(px + dr, 0.0f), IMG_W_F);
    float y2 = fminf(fmaxf(py + db, 0.0f), IMG_H_F);

    g_scores[gid] = s;
    g_labels[gid] = mi;
    float* b = &g_boxes[(size_t)gid * 4];
    b[0] = x1; b[1] = y1; b[2] = x2; b[3] = y2;
}

// ============ Kernel 2: per-batch radix-select of 1000th largest score ============
// scores >= 0 so float-bit ordering == numeric ordering.
__global__ void k_pivot() {
    int n = blockIdx.x;
    int tid = threadIdx.x;
    __shared__ int hist[256];
    __shared__ unsigned prefix;
    __shared__ int krem;
    __shared__ int gacc;
    if (tid == 0) { prefix = 0u; krem = PRE_K; gacc = 0; }
    __syncthreads();
    for (int r = 3; r >= 0; r--) {
        for (int i = tid; i < 256; i += blockDim.x) hist[i] = 0;
        __syncthreads();
        unsigned amask = (r == 3) ? 0u : (0xFFFFFFFFu << ((r + 1) * 8));
        unsigned pref = prefix;
        for (int p = tid; p < NP; p += blockDim.x) {
            unsigned b = __float_as_uint(g_scores[n * NP + p]);
            if ((b & amask) == (pref & amask))
                atomicAdd(&hist[(b >> (r * 8)) & 255], 1);
        }
        __syncthreads();
        if (tid == 0) {
            int acc = 0, sel = 0;
            for (int v = 255; v >= 0; v--) {
                acc += hist[v];
                if (acc >= krem) { sel = v; break; }
            }
            int above = acc - hist[sel];
            gacc += above;
            krem -= above;
            prefix |= (unsigned)sel << (r * 8);
        }
        __syncthreads();
    }
    if (tid == 0) { g_pivot[n] = prefix; g_gcnt[n] = gacc; }
}

// ============ Kernel 3: collect top-1000 candidates (equals in index order) ============
__global__ void k_collect() {
    int n = blockIdx.x;
    int tid = threadIdx.x;
    int lane = tid & 31;
    int warp = tid >> 5;
    unsigned piv = g_pivot[n];
    int G = g_gcnt[n];
    int need = PRE_K - G;

    __shared__ int cntG;
    __shared__ int eBase;
    __shared__ int wtot[32];
    __shared__ int wpre[32];
    __shared__ int totE;
    if (tid == 0) { cntG = 0; eBase = 0; }
    __syncthreads();

    for (int base = 0; base < NP; base += 1024) {
        int p = base + tid;
        bool inb = p < NP;
        unsigned b = inb ? __float_as_uint(g_scores[n * NP + p]) : 0u;
        if (inb && b > piv) {
            int pos = atomicAdd(&cntG, 1);
            g_cbits[n * 1024 + pos] = b;
            g_cidx [n * 1024 + pos] = p;
        }
        bool eq = inb && (b == piv);
        unsigned bal = __ballot_sync(0xFFFFFFFFu, eq);
        if (lane == 0) wtot[warp] = __popc(bal);
        __syncthreads();
        if (tid == 0) {
            int a = 0;
            for (int w = 0; w < 32; w++) { wpre[w] = a; a += wtot[w]; }
            totE = a;
        }
        __syncthreads();
        if (eq) {
            int rnk = eBase + wpre[warp] + __popc(bal & ((1u << lane) - 1u));
            if (rnk < need) {
                g_cbits[n * 1024 + G + rnk] = b;
                g_cidx [n * 1024 + G + rnk] = p;
            }
        }
        __syncthreads();
        if (tid == 0) eBase += totE;
        __syncthreads();
    }
    if (tid >= PRE_K) {                 // padding slots 1000..1023
        g_cbits[n * 1024 + tid] = 0u;
        g_cidx [n * 1024 + tid] = -1;   // ~(unsigned)(-1) == 0 -> smallest key
    }
}

// ============ Kernel 4: bitonic sort 1024 keys desc + gather top arrays ============
__global__ void k_sort() {
    __shared__ unsigned long long key[1024];
    int n = blockIdx.x;
    int tid = threadIdx.x;
    unsigned b = g_cbits[n * 1024 + tid];
    unsigned idx = (unsigned)g_cidx[n * 1024 + tid];
    key[tid] = ((unsigned long long)b << 32) | (unsigned)(~idx);
    __syncthreads();

    for (int k = 2; k <= 1024; k <<= 1) {
        for (int j = k >> 1; j > 0; j >>= 1) {
            int ixj = tid ^ j;
            if (ixj > tid) {
                unsigned long long a = key[tid], c = key[ixj];
                bool desc = (tid & k) == 0;
                if ((a < c) == desc) { key[tid] = c; key[ixj] = a; }
            }
            __syncthreads();
        }
    }
    if (tid < PRE_K) {
        unsigned long long kk = key[tid];
        int src_idx = (int)(~(unsigned)(kk & 0xFFFFFFFFull));
        float s = __uint_as_float((unsigned)(kk >> 32));
        int d = n * PRE_K + tid;
        g_tscore[d] = s;
        g_tlabel[d] = g_labels[n * NP + src_idx];
        const float* sb = &g_boxes[((size_t)n * NP + src_idx) * 4];
        float* db = &g_tbox[(size_t)d * 4];
        db[0] = sb[0]; db[1] = sb[1]; db[2] = sb[2]; db[3] = sb[3];
    }
}

// ============ Kernel 5: class-aware greedy NMS + top-100 + output ============
// dynamic smem: obox[1000*4] f, area[1000] f, mask[1000*32] u32, validw[32] u32,
//               sel[100] int, selk[100] int
__global__ void k_nms(float* out) {
    extern __shared__ unsigned char smraw[];
    float*    obox   = (float*)smraw;                  // 16000 B
    float*    area   = obox + PRE_K * 4;               // 4000 B
    unsigned* mask   = (unsigned*)(area + PRE_K);      // 128000 B
    unsigned* validw = mask + PRE_K * 32;              // 128 B
    int*      sel    = (int*)(validw + 32);            // 400 B
    int*      selk   = sel + POST_K;                   // 400 B

    int n = blockIdx.x;
    int tid = threadIdx.x;

    if (tid < PRE_K) {
        const float* b = &g_tbox[((size_t)n * PRE_K + tid) * 4];
        float o = (float)g_tlabel[n * PRE_K + tid] * CLS_OFF_F;
        float x1 = b[0] + o, y1 = b[1] + o, x2 = b[2] + o, y2 = b[3] + o;
        obox[tid * 4 + 0] = x1;
        obox[tid * 4 + 1] = y1;
        obox[tid * 4 + 2] = x2;
        obox[tid * 4 + 3] = y2;
        area[tid] = (x2 - x1) * (y2 - y1);
    }
    __syncthreads();

    // suppression mask: mask[i][w] bit bi set iff j = w*32+bi > i and iou(i,j) > thr
    for (int task = tid; task < PRE_K * 32; task += 1024) {
        int i = task >> 5;
        int w = task & 31;
        float ix1 = obox[i * 4 + 0], iy1 = obox[i * 4 + 1];
        float ix2 = obox[i * 4 + 2], iy2 = obox[i * 4 + 3];
        float ia = area[i];
        unsigned m = 0;
        int j0 = w * 32;
#pragma unroll 4
        for (int bi = 0; bi < 32; bi++) {
            int j = j0 + bi;
            if (j > i && j < PRE_K) {
                float xx1 = fmaxf(ix1, obox[j * 4 + 0]);
                float yy1 = fmaxf(iy1, obox[j * 4 + 1]);
                float xx2 = fminf(ix2, obox[j * 4 + 2]);
                float yy2 = fminf(iy2, obox[j * 4 + 3]);
                float iw = fmaxf(xx2 - xx1, 0.0f);
                float ih = fmaxf(yy2 - yy1, 0.0f);
                float inter = iw * ih;
                float iou = inter / (ia + area[j] - inter + 1e-9f);
                if (iou > IOU_THR_F) m |= (1u << bi);
            }
        }
        mask[i * 32 + w] = m;
    }
    __syncthreads();

    // serial greedy sweep, warp 0, lane owns valid word `lane`
    if (tid < 32) {
        unsigned v = 0;
        for (int bi = 0; bi < 32; bi++) {
            int j = tid * 32 + bi;
            if (j < PRE_K && g_tscore[n * PRE_K + j] > 0.0f) v |= (1u << bi);
        }
        for (int i = 0; i < PRE_K; i++) {
            unsigned vw = __shfl_sync(0xFFFFFFFFu, v, i >> 5);
            if ((vw >> (i & 31)) & 1u) v &= ~mask[i * 32 + tid];
        }
        validw[tid] = v;
    }
    __syncthreads();

    // stable partition: kept-in-order, then dropped-in-order; take first 100
    if (tid == 0) {
        int c = 0;
        for (int i = 0; i < PRE_K && c < POST_K; i++)
            if ((validw[i >> 5] >> (i & 31)) & 1u) { sel[c] = i; selk[c] = 1; c++; }
        for (int i = 0; i < PRE_K && c < POST_K; i++)
            if (!((validw[i >> 5] >> (i & 31)) & 1u)) { sel[c] = i; selk[c] = 0; c++; }
    }
    __syncthreads();

    if (tid < POST_K) {
        int i = sel[tid];
        int kept = selk[tid];
        int src = n * PRE_K + i;
        int dst = n * POST_K + tid;
        const float* b = &g_tbox[(size_t)src * 4];
        out[dst * 4 + 0] = b[0];
        out[dst * 4 + 1] = b[1];
        out[dst * 4 + 2] = b[2];
        out[dst * 4 + 3] = b[3];
        out[NB * POST_K * 4 + dst] = kept ? g_tscore[src] : 0.0f;                 // scores
        out[NB * POST_K * 4 + NB * POST_K + dst] = (float)g_tlabel[src];          // labels
    }
}

// ---------------- host launch ----------------
extern "C" void kernel_launch(void* const* d_in, const int* in_sizes, int n_in,
                              void* d_out, int out_size) {
    (void)in_sizes; (void)n_in; (void)out_size;

    Ptrs p;
    for (int l = 0; l < 5; l++) {
        p.cls[l] = (const float*)d_in[3 * l + 0];
        p.reg[l] = (const float*)d_in[3 * l + 1];
        p.ctr[l] = (const float*)d_in[3 * l + 2];
    }
    float* out = (float*)d_out;

    // NMS needs large dynamic smem
    static bool attr_set = false;
    if (!attr_set) {
        cudaFuncSetAttribute(k_nms, cudaFuncAttributeMaxDynamicSharedMemorySize, 160 * 1024);
        attr_set = true;
    }
    const int smem_nms = PRE_K * 4 * 4 + PRE_K * 4 + PRE_K * 32 * 4 + 32 * 4
                       + POST_K * 4 * 2;

    int total = NB * NP;
    k_decode<<<(total + 255) / 256, 256>>>(p);
    k_pivot<<<NB, 256>>>();
    k_collect<<<NB, 1024>>>();
    k_sort<<<NB, 1024>>>();
    k_nms<<<NB, 1024, smem_nms>>>(out);
}

// round 2
// speedup vs baseline: 2.1351x; 2.1351x over previous
#include <cuda_runtime.h>
#include <cuda_bf16.h>
#include <cstdint>

// ---------------- problem constants ----------------
#define NB 16        // batch
#define NC 80        // classes
#define NP 17064     // total locations across 5 levels
#define PRE_K 1000
#define POST_K 100
#define IMG_W_F 1024.0f
#define IMG_H_F 800.0f
#define THRESH_F 0.05f
#define IOU_THR_F 0.6f
#define CLS_OFF_F 4096.0f

struct Ptrs {
    const float* cls[5];
    const float* reg[5];
    const float* ctr[5];
};

// ---------------- device scratch (static, no allocs) ----------------
__device__ float    g_scores[NB * NP];
__device__ int      g_labels[NB * NP];
__device__ float    g_boxes [NB * NP * 4];
__device__ unsigned g_pivot [NB];
__device__ int      g_gcnt  [NB];
__device__ unsigned g_cbits [NB * 1024];
__device__ int      g_cidx  [NB * 1024];
__device__ float    g_tscore[NB * PRE_K];
__device__ int      g_tlabel[NB * PRE_K];
__device__ float    g_tbox  [NB * PRE_K * 4];
__device__ unsigned g_mask  [NB * PRE_K * 32];   // suppression bitmask (global, L2-resident)

__device__ __forceinline__ float sigmoidf_(float x) {
    return 1.0f / (1.0f + expf(-x));
}

// ============ Kernel 1: decode scores/labels/boxes per location ============
__global__ void k_decode(Ptrs p) {
    int gid = blockIdx.x * blockDim.x + threadIdx.x;
    if (gid >= NB * NP) return;
    int n = gid / NP;
    int loc = gid - n * NP;

    int l, off, ww, stride, hw;
    if (loc < 12800)      { l = 0; off = 0;     ww = 128; stride = 8;   hw = 12800; }
    else if (loc < 16000) { l = 1; off = 12800; ww = 64;  stride = 16;  hw = 3200;  }
    else if (loc < 16800) { l = 2; off = 16000; ww = 32;  stride = 32;  hw = 800;   }
    else if (loc < 17008) { l = 3; off = 16800; ww = 16;  stride = 64;  hw = 208;   }
    else                  { l = 4; off = 17008; ww = 8;   stride = 128; hw = 56;    }

    int local = loc - off;
    int y = local / ww;
    int x = local - y * ww;

    // argmax over class logits (sigmoid monotone => same argmax as scores)
    const float* cls = p.cls[l] + (size_t)n * NC * hw + local;
    float m = cls[0];
    int mi = 0;
#pragma unroll 8
    for (int c = 1; c < NC; c++) {
        float v = __ldg(&cls[(size_t)c * hw]);
        if (v > m) { m = v; mi = c; }
    }
    float ctr = p.ctr[l][(size_t)n * hw + local];
    float s = sqrtf(sigmoidf_(m) * sigmoidf_(ctr));
    if (!(s > THRESH_F)) s = 0.0f;

    const float* reg = p.reg[l] + (size_t)n * 4 * hw + local;
    float dl = reg[0];
    float dt = reg[hw];
    float dr = reg[2 * hw];
    float db = reg[3 * hw];

    float px = (float)x * (float)stride + 0.5f * (float)stride;
    float py = (float)y * (float)stride + 0.5f * (float)stride;

    float x1 = fminf(fmaxf(px - dl, 0.0f), IMG_W_F);
    float y1 = fminf(fmaxf(py - dt, 0.0f), IMG_H_F);
    float x2 = fminf(fmaxf(px + dr, 0.0f), IMG_W_F);
    float y2 = fminf(fmaxf(py + db, 0.0f), IMG_H_F);

    g_scores[gid] = s;
    g_labels[gid] = mi;
    float* b = &g_boxes[(size_t)gid * 4];
    b[0] = x1; b[1] = y1; b[2] = x2; b[3] = y2;
}

// ============ Kernel 2: per-batch radix-select of 1000th largest score ============
// scores >= 0 so float-bit ordering == numeric ordering.
__global__ void k_pivot() {
    int n = blockIdx.x;
    int tid = threadIdx.x;
    __shared__ int hist[256];
    __shared__ unsigned prefix;
    __shared__ int krem;
    __shared__ int gacc;
    if (tid == 0) { prefix = 0u; krem = PRE_K; gacc = 0; }
    __syncthreads();
    for (int r = 3; r >= 0; r--) {
        for (int i = tid; i < 256; i += blockDim.x) hist[i] = 0;
        __syncthreads();
        unsigned amask = (r == 3) ? 0u : (0xFFFFFFFFu << ((r + 1) * 8));
        unsigned pref = prefix;
        for (int p = tid; p < NP; p += blockDim.x) {
            unsigned b = __float_as_uint(g_scores[n * NP + p]);
            if ((b & amask) == (pref & amask))
                atomicAdd(&hist[(b >> (r * 8)) & 255], 1);
        }
        __syncthreads();
        if (tid == 0) {
            int acc = 0, sel = 0;
            for (int v = 255; v >= 0; v--) {
                acc += hist[v];
                if (acc >= krem) { sel = v; break; }
            }
            int above = acc - hist[sel];
            gacc += above;
            krem -= above;
            prefix |= (unsigned)sel << (r * 8);
        }
        __syncthreads();
    }
    if (tid == 0) { g_pivot[n] = prefix; g_gcnt[n] = gacc; }
}

// ============ Kernel 3: collect top-1000 candidates (equals in index order) ============
__global__ void k_collect() {
    int n = blockIdx.x;
    int tid = threadIdx.x;
    int lane = tid & 31;
    int warp = tid >> 5;
    unsigned piv = g_pivot[n];
    int G = g_gcnt[n];
    int need = PRE_K - G;

    __shared__ int cntG;
    __shared__ int eBase;
    __shared__ int wtot[32];
    __shared__ int wpre[32];
    __shared__ int totE;
    if (tid == 0) { cntG = 0; eBase = 0; }
    __syncthreads();

    for (int base = 0; base < NP; base += 1024) {
        int p = base + tid;
        bool inb = p < NP;
        unsigned b = inb ? __float_as_uint(g_scores[n * NP + p]) : 0u;
        if (inb && b > piv) {
            int pos = atomicAdd(&cntG, 1);
            g_cbits[n * 1024 + pos] = b;
            g_cidx [n * 1024 + pos] = p;
        }
        bool eq = inb && (b == piv);
        unsigned bal = __ballot_sync(0xFFFFFFFFu, eq);
        if (lane == 0) wtot[warp] = __popc(bal);
        __syncthreads();
        if (tid == 0) {
            int a = 0;
            for (int w = 0; w < 32; w++) { wpre[w] = a; a += wtot[w]; }
            totE = a;
        }
        __syncthreads();
        if (eq) {
            int rnk = eBase + wpre[warp] + __popc(bal & ((1u << lane) - 1u));
            if (rnk < need) {
                g_cbits[n * 1024 + G + rnk] = b;
                g_cidx [n * 1024 + G + rnk] = p;
            }
        }
        __syncthreads();
        if (tid == 0) eBase += totE;
        __syncthreads();
    }
    if (tid >= PRE_K) {                 // padding slots 1000..1023
        g_cbits[n * 1024 + tid] = 0u;
        g_cidx [n * 1024 + tid] = -1;   // ~(unsigned)(-1) == 0 -> smallest key
    }
}

// ============ Kernel 4: bitonic sort 1024 keys desc + gather top arrays ============
__global__ void k_sort() {
    __shared__ unsigned long long key[1024];
    int n = blockIdx.x;
    int tid = threadIdx.x;
    unsigned b = g_cbits[n * 1024 + tid];
    unsigned idx = (unsigned)g_cidx[n * 1024 + tid];
    key[tid] = ((unsigned long long)b << 32) | (unsigned)(~idx);
    __syncthreads();

    for (int k = 2; k <= 1024; k <<= 1) {
        for (int j = k >> 1; j > 0; j >>= 1) {
            int ixj = tid ^ j;
            if (ixj > tid) {
                unsigned long long a = key[tid], c = key[ixj];
                bool desc = (tid & k) == 0;
                if ((a < c) == desc) { key[tid] = c; key[ixj] = a; }
            }
            __syncthreads();
        }
    }
    if (tid < PRE_K) {
        unsigned long long kk = key[tid];
        int src_idx = (int)(~(unsigned)(kk & 0xFFFFFFFFull));
        float s = __uint_as_float((unsigned)(kk >> 32));
        int d = n * PRE_K + tid;
        g_tscore[d] = s;
        g_tlabel[d] = g_labels[n * NP + src_idx];
        const float* sb = &g_boxes[((size_t)n * NP + src_idx) * 4];
        float* db = &g_tbox[(size_t)d * 4];
        db[0] = sb[0]; db[1] = sb[1]; db[2] = sb[2]; db[3] = sb[3];
    }
}

// ============ Kernel 5a: suppression mask (warp-per-j-chunk, j-boxes in regs) ============
// grid (NB, 8): block (n, iblk) handles i in [iblk*125, iblk*125+125).
// Warp w owns j = w*32+lane (registers). One broadcast LDS.128 per i. Ballot -> mask word.
__global__ void k_mask() {
    __shared__ float4 sbox[1024];
    int n = blockIdx.x;
    int iblk = blockIdx.y;
    int tid = threadIdx.x;

    // load class-offset boxes into smem (padded to 1024)
    for (int i = tid; i < 1024; i += blockDim.x) {
        float4 b;
        if (i < PRE_K) {
            b = *(const float4*)&g_tbox[((size_t)n * PRE_K + i) * 4];
            float o = (float)g_tlabel[n * PRE_K + i] * CLS_OFF_F;
            b.x += o; b.y += o; b.z += o; b.w += o;
        } else {
            b = make_float4(0.f, 0.f, 0.f, 0.f);
        }
        sbox[i] = b;
    }
    __syncthreads();

    int w = tid >> 5;
    int lane = tid & 31;
    int j = w * 32 + lane;
    float4 jb = sbox[j];
    float ja = (jb.z - jb.x) * (jb.w - jb.y);

    int i0 = iblk * 125;
    int i1 = i0 + 125;
    for (int i = i0; i < i1; i++) {
        if (w * 32 + 31 <= i) continue;          // triangular skip (warp-uniform)
        float4 ib = sbox[i];                      // broadcast, conflict-free
        float ia = (ib.z - ib.x) * (ib.w - ib.y);
        float xx1 = fmaxf(ib.x, jb.x);
        float yy1 = fmaxf(ib.y, jb.y);
        float xx2 = fminf(ib.z, jb.z);
        float yy2 = fminf(ib.w, jb.w);
        float iw = fmaxf(xx2 - xx1, 0.0f);
        float ih = fmaxf(yy2 - yy1, 0.0f);
        float inter = iw * ih;
        float iou = inter / (ia + ja - inter + 1e-9f);
        bool c = (iou > IOU_THR_F) && (j > i) && (j < PRE_K);
        unsigned bal = __ballot_sync(0xFFFFFFFFu, c);
        if (lane == 0) g_mask[((size_t)n * PRE_K + i) * 32 + w] = bal;
    }
}

// ============ Kernel 5b: greedy sweep + stable partition + output ============
__global__ void k_sweep(float* out) {
    __shared__ unsigned s_valid;   // unused placeholder (keeps struct simple)
    __shared__ int s_sel [POST_K];
    __shared__ int s_kept[POST_K];
    (void)s_valid;

    int n = blockIdx.x;
    int tid = threadIdx.x;
    int lane = tid & 31;
    const unsigned FULL = 0xFFFFFFFFu;

    if (tid < 32) {
        // init valid bits: lane L owns word L (bits j = L*32 + b); coalesced ballots
        unsigned v = 0;
        for (int W = 0; W < 32; W++) {
            int idx = W * 32 + lane;
            float sc = (idx < PRE_K) ? g_tscore[n * PRE_K + idx] : 0.0f;
            unsigned bal = __ballot_sync(FULL, sc > 0.0f);
            if (lane == W) v = bal;
        }

        // greedy sweep, word at a time
        for (int W = 0; W < 32; W++) {
            unsigned vw = __shfl_sync(FULL, v, W);
            // self-mask word for each i in this word: mask[i][W]
            int idx = W * 32 + lane;
            unsigned smv = (idx < PRE_K) ? g_mask[((size_t)n * PRE_K + idx) * 32 + W] : 0u;
            unsigned sm[32];
#pragma unroll
            for (int b = 0; b < 32; b++) sm[b] = __shfl_sync(FULL, smv, b);
            // register-only within-word greedy closure (every lane computes redundantly)
            unsigned alive = vw;
#pragma unroll
            for (int b = 0; b < 32; b++)
                if ((alive >> b) & 1u) alive &= ~sm[b];
            if (lane == W) v = alive;
            // cross-word suppression from kept i's (independent loads, MLP-covered)
            unsigned rem = alive;
            while (rem) {
                int b = __ffs(rem) - 1;
                rem &= rem - 1;
                int i = W * 32 + b;
                unsigned row = (lane > W) ? g_mask[((size_t)n * PRE_K + i) * 32 + lane] : 0u;
                v &= ~row;
            }
        }

        // stable partition (kept in index order, then dropped in index order)
        int c = __popc(v);
        int incl = c;
        for (int d = 1; d < 32; d <<= 1) {
            int t = __shfl_up_sync(FULL, incl, d);
            if (lane >= d) incl += t;
        }
        int pre = incl - c;                       // kept count in lanes < this
        int totK = __shfl_sync(FULL, incl, 31);   // total kept
        for (int b = 0; b < 32; b++) {
            int i = lane * 32 + b;
            if (i >= PRE_K) break;
            bool kept = (v >> b) & 1u;
            int kb = pre + __popc(v & ((1u << b) - 1u));   // kept strictly before i
            int pos = kept ? kb : (totK + (i - kb));        // dropped rank = i - kept_before
            if (pos < POST_K) { s_sel[pos] = i; s_kept[pos] = kept ? 1 : 0; }
        }
    }
    __syncthreads();

    if (tid < POST_K) {
        int i = s_sel[tid];
        int kept = s_kept[tid];
        int src = n * PRE_K + i;
        int dst = n * POST_K + tid;
        float4 b = *(const float4*)&g_tbox[(size_t)src * 4];
        ((float4*)out)[dst] = b;
        out[NB * POST_K * 4 + dst] = kept ? g_tscore[src] : 0.0f;          // scores
        out[NB * POST_K * 4 + NB * POST_K + dst] = (float)g_tlabel[src];   // labels
    }
}

// ---------------- host launch ----------------
extern "C" void kernel_launch(void* const* d_in, const int* in_sizes, int n_in,
                              void* d_out, int out_size) {
    (void)in_sizes; (void)n_in; (void)out_size;

    Ptrs p;
    for (int l = 0; l < 5; l++) {
        p.cls[l] = (const float*)d_in[3 * l + 0];
        p.reg[l] = (const float*)d_in[3 * l + 1];
        p.ctr[l] = (const float*)d_in[3 * l + 2];
    }
    float* out = (float*)d_out;

    int total = NB * NP;
    k_decode<<<(total + 255) / 256, 256>>>(p);
    k_pivot<<<NB, 256>>>();
    k_collect<<<NB, 1024>>>();
    k_sort<<<NB, 1024>>>();
    k_mask<<<dim3(NB, 8), 1024>>>();
    k_sweep<<<NB, 128>>>(out);
}

// round 5
// speedup vs baseline: 2.3973x; 1.1228x over previous
#include <cuda_runtime.h>
#include <cuda_bf16.h>
#include <cstdint>

// ---------------- problem constants ----------------
#define NB 16        // batch
#define NC 80        // classes
#define NP 17064     // total locations across 5 levels
#define NP4 (NP / 4) // 4266
#define PRE_K 1000
#define POST_K 100
#define IMG_W_F 1024.0f
#define IMG_H_F 800.0f
#define THRESH_F 0.05f
#define IOU_THR_F 0.6f
#define CLS_OFF_F 4096.0f

struct Ptrs {
    const float* cls[5];
    const float* reg[5];
    const float* ctr[5];
};

// ---------------- device scratch (static, no allocs) ----------------
__device__ float    g_scores[NB * NP];
__device__ int      g_labels[NB * NP];
__device__ float    g_boxes [NB * NP * 4];
__device__ unsigned g_cbits [NB * 1024];
__device__ int      g_cidx  [NB * 1024];
__device__ float    g_tscore[NB * PRE_K];
__device__ int      g_tlabel[NB * PRE_K];
__device__ float    g_tbox  [NB * PRE_K * 4];
__device__ unsigned g_mask  [NB * PRE_K * 32];   // suppression bitmask (global, L2-resident)

__device__ __forceinline__ float sigmoidf_(float x) {
    return 1.0f / (1.0f + expf(-x));
}

// ============ Kernel 1: decode, 4 consecutive locations per thread ============
__global__ void k_decode(Ptrs p) {
    int gid = blockIdx.x * blockDim.x + threadIdx.x;
    if (gid >= NB * NP4) return;
    int n = gid / NP4;
    int loc = (gid - n * NP4) * 4;

    int l, off, ww, stride, hw;
    if (loc < 12800)      { l = 0; off = 0;     ww = 128; stride = 8;   hw = 12800; }
    else if (loc < 16000) { l = 1; off = 12800; ww = 64;  stride = 16;  hw = 3200;  }
    else if (loc < 16800) { l = 2; off = 16000; ww = 32;  stride = 32;  hw = 800;   }
    else if (loc < 17008) { l = 3; off = 16800; ww = 16;  stride = 64;  hw = 208;   }
    else                  { l = 4; off = 17008; ww = 8;   stride = 128; hw = 56;    }

    int local = loc - off;               // multiple of 4; ww % 4 == 0 -> same row
    int y = local / ww;
    int x = local - y * ww;

    // argmax over class logits for 4 locations (sigmoid monotone)
    const float4* cls = (const float4*)(p.cls[l] + (size_t)n * NC * hw + local);
    size_t cstride = (size_t)hw / 4;     // float4 stride between classes
    float4 m = __ldg(&cls[0]);
    int mi0 = 0, mi1 = 0, mi2 = 0, mi3 = 0;
#pragma unroll 4
    for (int c = 1; c < NC; c++) {
        float4 v = __ldg(&cls[(size_t)c * cstride]);
        if (v.x > m.x) { m.x = v.x; mi0 = c; }
        if (v.y > m.y) { m.y = v.y; mi1 = c; }
        if (v.z > m.z) { m.z = v.z; mi2 = c; }
        if (v.w > m.w) { m.w = v.w; mi3 = c; }
    }

    float4 ctr = __ldg((const float4*)(p.ctr[l] + (size_t)n * hw + local));
    const float* reg = p.reg[l] + (size_t)n * 4 * hw + local;
    float4 dl = __ldg((const float4*)(reg));
    float4 dt = __ldg((const float4*)(reg + hw));
    float4 dr = __ldg((const float4*)(reg + 2 * hw));
    float4 db = __ldg((const float4*)(reg + 3 * hw));

    float py = (float)y * (float)stride + 0.5f * (float)stride;
    float sc[4]; int lab[4]; float4 box[4];
    float mv[4] = {m.x, m.y, m.z, m.w};
    int   mic[4] = {mi0, mi1, mi2, mi3};
    float ctv[4] = {ctr.x, ctr.y, ctr.z, ctr.w};
    float dlv[4] = {dl.x, dl.y, dl.z, dl.w};
    float dtv[4] = {dt.x, dt.y, dt.z, dt.w};
    float drv[4] = {dr.x, dr.y, dr.z, dr.w};
    float dbv[4] = {db.x, db.y, db.z, db.w};
#pragma unroll
    for (int k = 0; k < 4; k++) {
        float s = sqrtf(sigmoidf_(mv[k]) * sigmoidf_(ctv[k]));
        if (!(s > THRESH_F)) s = 0.0f;
        float px = (float)(x + k) * (float)stride + 0.5f * (float)stride;
        float x1 = fminf(fmaxf(px - dlv[k], 0.0f), IMG_W_F);
        float y1 = fminf(fmaxf(py - dtv[k], 0.0f), IMG_H_F);
        float x2 = fminf(fmaxf(px + drv[k], 0.0f), IMG_W_F);
        float y2 = fminf(fmaxf(py + dbv[k], 0.0f), IMG_H_F);
        sc[k] = s; lab[k] = mic[k];
        box[k] = make_float4(x1, y1, x2, y2);
    }

    int base = n * NP + loc;
    *(float4*)&g_scores[base] = make_float4(sc[0], sc[1], sc[2], sc[3]);
    *(int4*)&g_labels[base]   = make_int4(lab[0], lab[1], lab[2], lab[3]);
    float4* bout = (float4*)&g_boxes[(size_t)base * 4];
    bout[0] = box[0]; bout[1] = box[1]; bout[2] = box[2]; bout[3] = box[3];
}

// ============ Kernel 2: fused radix pivot + candidate collect (per batch) ============
// scores >= 0 so float-bit ordering == numeric ordering.
__global__ void k_select() {
    int n = blockIdx.x;
    int tid = threadIdx.x;
    int lane = tid & 31;
    int warp = tid >> 5;
    const unsigned FULL = 0xFFFFFFFFu;

    __shared__ int hist[256];
    __shared__ unsigned s_prefix;
    __shared__ int s_krem;
    __shared__ int s_gacc;
    if (tid == 0) { s_prefix = 0u; s_krem = PRE_K; s_gacc = 0; }
    __syncthreads();

    // ---- 4-round radix select of 1000th-largest score ----
    for (int r = 3; r >= 0; r--) {
        for (int i = tid; i < 256; i += blockDim.x) hist[i] = 0;
        __syncthreads();
        unsigned amask = (r == 3) ? 0u : (0xFFFFFFFFu << ((r + 1) * 8));
        unsigned pref = s_prefix;
        for (int p = tid; p < NP; p += blockDim.x) {
            unsigned b = __float_as_uint(g_scores[n * NP + p]);
            if ((b & amask) == (pref & amask))
                atomicAdd(&hist[(b >> (r * 8)) & 255], 1);
        }
        __syncthreads();
        // warp 0: parallel boundary search over 256 bins, descending
        if (warp == 0) {
            // lane L owns descending chunk of 8 bins: v in [255-8L .. 248-8L]
            int top = 255 - 8 * lane;
            int csum = 0;
#pragma unroll
            for (int k = 0; k < 8; k++) csum += hist[top - k];
            // exclusive prefix over lanes (sum of chunks with higher bins)
            int pre = 0;
            {
                int inc = csum;
                for (int d = 1; d < 32; d <<= 1) {
                    int t = __shfl_up_sync(FULL, inc, d);
                    if (lane >= d) inc += t;
                }
                pre = inc - csum;
            }
            int krem = s_krem;
            bool mine = (pre < krem) && (pre + csum >= krem);
            if (mine) {
                int acc = pre, sel = top - 7;
                for (int k = 0; k < 8; k++) {
                    acc += hist[top - k];
                    if (acc >= krem) { sel = top - k; break; }
                }
                int above = acc - hist[sel];
                s_gacc += above;
                s_krem = krem - above;
                s_prefix |= (unsigned)sel << (r * 8);
            }
        }
        __syncthreads();
    }

    unsigned piv = s_prefix;
    int G = s_gacc;
    int need = PRE_K - G;

    // ---- collect: strictly-greater anywhere, equals in index order ----
    __shared__ int cntG;
    __shared__ int eBase;
    __shared__ int wtot[32];
    __shared__ int wpre[32];
    __shared__ int totE;
    if (tid == 0) { cntG = 0; eBase = 0; }
    __syncthreads();

    for (int base = 0; base < NP; base += 1024) {
        int p = base + tid;
        bool inb = p < NP;
        unsigned b = inb ? __float_as_uint(g_scores[n * NP + p]) : 0u;
        if (inb && b > piv) {
            int pos = atomicAdd(&cntG, 1);
            g_cbits[n * 1024 + pos] = b;
            g_cidx [n * 1024 + pos] = p;
        }
        bool eq = inb && (b == piv);
        unsigned bal = __ballot_sync(FULL, eq);
        if (lane == 0) wtot[warp] = __popc(bal);
        __syncthreads();
        if (tid == 0) {
            int a = 0;
            for (int w = 0; w < 32; w++) { wpre[w] = a; a += wtot[w]; }
            totE = a;
        }
        __syncthreads();
        if (eq) {
            int rnk = eBase + wpre[warp] + __popc(bal & ((1u << lane) - 1u));
            if (rnk < need) {
                g_cbits[n * 1024 + G + rnk] = b;
                g_cidx [n * 1024 + G + rnk] = p;
            }
        }
        __syncthreads();
        if (tid == 0) eBase += totE;
        __syncthreads();
    }
    if (tid >= PRE_K) {                 // padding slots 1000..1023
        g_cbits[n * 1024 + tid] = 0u;
        g_cidx [n * 1024 + tid] = -1;   // ~(unsigned)(-1) == 0 -> smallest key
    }
}

// ============ Kernel 3: bitonic sort 1024 keys desc + gather top arrays ============
__global__ void k_sort() {
    __shared__ unsigned long long key[1024];
    int n = blockIdx.x;
    int tid = threadIdx.x;
    unsigned b = g_cbits[n * 1024 + tid];
    unsigned idx = (unsigned)g_cidx[n * 1024 + tid];
    key[tid] = ((unsigned long long)b << 32) | (unsigned)(~idx);
    __syncthreads();

    for (int k = 2; k <= 1024; k <<= 1) {
        for (int j = k >> 1; j > 0; j >>= 1) {
            int ixj = tid ^ j;
            if (ixj > tid) {
                unsigned long long a = key[tid], c = key[ixj];
                bool desc = (tid & k) == 0;
                if ((a < c) == desc) { key[tid] = c; key[ixj] = a; }
            }
            __syncthreads();
        }
    }
    if (tid < PRE_K) {
        unsigned long long kk = key[tid];
        int src_idx = (int)(~(unsigned)(kk & 0xFFFFFFFFull));
        float s = __uint_as_float((unsigned)(kk >> 32));
        int d = n * PRE_K + tid;
        g_tscore[d] = s;
        g_tlabel[d] = g_labels[n * NP + src_idx];
        const float* sb = &g_boxes[((size_t)n * NP + src_idx) * 4];
        float* db = &g_tbox[(size_t)d * 4];
        db[0] = sb[0]; db[1] = sb[1]; db[2] = sb[2]; db[3] = sb[3];
    }
}

// ============ Kernel 4a: suppression mask (warp-per-j-chunk, j-boxes in regs) ============
__global__ void k_mask() {
    __shared__ float4 sbox[1024];
    int n = blockIdx.x;
    int iblk = blockIdx.y;
    int tid = threadIdx.x;

    for (int i = tid; i < 1024; i += blockDim.x) {
        float4 b;
        if (i < PRE_K) {
            b = *(const float4*)&g_tbox[((size_t)n * PRE_K + i) * 4];
            float o = (float)g_tlabel[n * PRE_K + i] * CLS_OFF_F;
            b.x += o; b.y += o; b.z += o; b.w += o;
        } else {
            b = make_float4(0.f, 0.f, 0.f, 0.f);
        }
        sbox[i] = b;
    }
    __syncthreads();

    int w = tid >> 5;
    int lane = tid & 31;
    int j = w * 32 + lane;
    float4 jb = sbox[j];
    float ja = (jb.z - jb.x) * (jb.w - jb.y);

    int i0 = iblk * 125;
    int i1 = i0 + 125;
    for (int i = i0; i < i1; i++) {
        if (w * 32 + 31 <= i) continue;          // triangular skip (warp-uniform)
        float4 ib = sbox[i];                      // broadcast, conflict-free
        float ia = (ib.z - ib.x) * (ib.w - ib.y);
        float xx1 = fmaxf(ib.x, jb.x);
        float yy1 = fmaxf(ib.y, jb.y);
        float xx2 = fminf(ib.z, jb.z);
        float yy2 = fminf(ib.w, jb.w);
        float iw = fmaxf(xx2 - xx1, 0.0f);
        float ih = fmaxf(yy2 - yy1, 0.0f);
        float inter = iw * ih;
        float iou = inter / (ia + ja - inter + 1e-9f);
        bool c = (iou > IOU_THR_F) && (j > i) && (j < PRE_K);
        unsigned bal = __ballot_sync(0xFFFFFFFFu, c);
        if (lane == 0) g_mask[((size_t)n * PRE_K + i) * 32 + w] = bal;
    }
}

// ============ Kernel 4b: greedy sweep + stable partition + output ============
__global__ void k_sweep(float* out) {
    __shared__ int s_sel [POST_K];
    __shared__ int s_kept[POST_K];

    int n = blockIdx.x;
    int tid = threadIdx.x;
    int lane = tid & 31;
    const unsigned FULL = 0xFFFFFFFFu;

    if (tid < 32) {
        unsigned v = 0;
        for (int W = 0; W < 32; W++) {
            int idx = W * 32 + lane;
            float sc = (idx < PRE_K) ? g_tscore[n * PRE_K + idx] : 0.0f;
            unsigned bal = __ballot_sync(FULL, sc > 0.0f);
            if (lane == W) v = bal;
        }

        for (int W = 0; W < 32; W++) {
            unsigned vw = __shfl_sync(FULL, v, W);
            int idx = W * 32 + lane;
            unsigned smv = (idx < PRE_K) ? g_mask[((size_t)n * PRE_K + idx) * 32 + W] : 0u;
            unsigned sm[32];
#pragma unroll
            for (int b = 0; b < 32; b++) sm[b] = __shfl_sync(FULL, smv, b);
            unsigned alive = vw;
#pragma unroll
            for (int b = 0; b < 32; b++)
                if ((alive >> b) & 1u) alive &= ~sm[b];
            if (lane == W) v = alive;
            unsigned rem = alive;
            while (rem) {
                int b = __ffs(rem) - 1;
                rem &= rem - 1;
                int i = W * 32 + b;
                unsigned row = (lane > W) ? g_mask[((size_t)n * PRE_K + i) * 32 + lane] : 0u;
                v &= ~row;
            }
        }

        // stable partition (kept in index order, then dropped in index order)
        int c = __popc(v);
        int incl = c;
        for (int d = 1; d < 32; d <<= 1) {
            int t = __shfl_up_sync(FULL, incl, d);
            if (lane >= d) incl += t;
        }
        int pre = incl - c;
        int totK = __shfl_sync(FULL, incl, 31);
        for (int b = 0; b < 32; b++) {
            int i = lane * 32 + b;
            if (i >= PRE_K) break;
            bool kept = (v >> b) & 1u;
            int kb = pre + __popc(v & ((1u << b) - 1u));
            int pos = kept ? kb : (totK + (i - kb));
            if (pos < POST_K) { s_sel[pos] = i; s_kept[pos] = kept ? 1 : 0; }
        }
    }
    __syncthreads();

    if (tid < POST_K) {
        int i = s_sel[tid];
        int kept = s_kept[tid];
        int src = n * PRE_K + i;
        int dst = n * POST_K + tid;
        float4 b = *(const float4*)&g_tbox[(size_t)src * 4];
        ((float4*)out)[dst] = b;
        out[NB * POST_K * 4 + dst] = kept ? g_tscore[src] : 0.0f;          // scores
        out[NB * POST_K * 4 + NB * POST_K + dst] = (float)g_tlabel[src];   // labels
    }
}

// ---------------- host launch ----------------
extern "C" void kernel_launch(void* const* d_in, const int* in_sizes, int n_in,
                              void* d_out, int out_size) {
    (void)in_sizes; (void)n_in; (void)out_size;

    Ptrs p;
    for (int l = 0; l < 5; l++) {
        p.cls[l] = (const float*)d_in[3 * l + 0];
        p.reg[l] = (const float*)d_in[3 * l + 1];
        p.ctr[l] = (const float*)d_in[3 * l + 2];
    }
    float* out = (float*)d_out;

    int total = NB * NP4;
    k_decode<<<(total + 255) / 256, 256>>>(p);
    k_select<<<NB, 1024>>>();
    k_sort<<<NB, 1024>>>();
    k_mask<<<dim3(NB, 8), 1024>>>();
    k_sweep<<<NB, 128>>>(out);
}

// round 7
// speedup vs baseline: 2.4850x; 1.0366x over previous
#include <cuda_runtime.h>
#include <cuda_bf16.h>
#include <cstdint>

// ---------------- problem constants ----------------
#define NB 16        // batch
#define NC 80        // classes
#define NP 17064     // total locations across 5 levels
#define NP4 (NP / 4) // 4266
#define PRE_K 1000
#define POST_K 100
#define CAND 2048
#define HBINS 4096
#define IMG_W_F 1024.0f
#define IMG_H_F 800.0f
#define THRESH_F 0.05f
#define IOU_THR_F 0.6f
#define CLS_OFF_F 4096.0f

struct Ptrs {
    const float* cls[5];
    const float* reg[5];
    const float* ctr[5];
};

// ---------------- device scratch (static, no allocs; zero-initialized) ----------------
__device__ float    g_scores[NB * NP];
__device__ int      g_labels[NB * NP];
__device__ float    g_boxes [NB * NP * 4];
__device__ float    g_tscore[NB * PRE_K];
__device__ int      g_tlabel[NB * PRE_K];
__device__ float    g_tbox  [NB * PRE_K * 4];
__device__ unsigned g_mask  [NB * PRE_K * 32];   // unwritten words stay 0 (no j>i bits there)
__device__ unsigned g_validw[NB * 32];

__device__ __forceinline__ float sigmoidf_(float x) {
    return 1.0f / (1.0f + expf(-x));
}

// ============ Kernel 1: decode, 4 consecutive locations per thread ============
__global__ void k_decode(Ptrs p) {
    int gid = blockIdx.x * blockDim.x + threadIdx.x;
    if (gid >= NB * NP4) return;
    int n = gid / NP4;
    int loc = (gid - n * NP4) * 4;

    int l, off, ww, stride, hw;
    if (loc < 12800)      { l = 0; off = 0;     ww = 128; stride = 8;   hw = 12800; }
    else if (loc < 16000) { l = 1; off = 12800; ww = 64;  stride = 16;  hw = 3200;  }
    else if (loc < 16800) { l = 2; off = 16000; ww = 32;  stride = 32;  hw = 800;   }
    else if (loc < 17008) { l = 3; off = 16800; ww = 16;  stride = 64;  hw = 208;   }
    else                  { l = 4; off = 17008; ww = 8;   stride = 128; hw = 56;    }

    int local = loc - off;               // multiple of 4; ww % 4 == 0 -> same row
    int y = local / ww;
    int x = local - y * ww;

    // argmax over class logits for 4 locations (sigmoid monotone)
    const float4* cls = (const float4*)(p.cls[l] + (size_t)n * NC * hw + local);
    size_t cstride = (size_t)hw / 4;     // float4 stride between classes
    float4 m = __ldg(&cls[0]);
    int mi0 = 0, mi1 = 0, mi2 = 0, mi3 = 0;
#pragma unroll 16
    for (int c = 1; c < NC; c++) {
        float4 v = __ldg(&cls[(size_t)c * cstride]);
        if (v.x > m.x) { m.x = v.x; mi0 = c; }
        if (v.y > m.y) { m.y = v.y; mi1 = c; }
        if (v.z > m.z) { m.z = v.z; mi2 = c; }
        if (v.w > m.w) { m.w = v.w; mi3 = c; }
    }

    float4 ctr = __ldg((const float4*)(p.ctr[l] + (size_t)n * hw + local));
    const float* reg = p.reg[l] + (size_t)n * 4 * hw + local;
    float4 dl = __ldg((const float4*)(reg));
    float4 dt = __ldg((const float4*)(reg + hw));
    float4 dr = __ldg((const float4*)(reg + 2 * hw));
    float4 db = __ldg((const float4*)(reg + 3 * hw));

    float py = (float)y * (float)stride + 0.5f * (float)stride;
    float sc[4]; int lab[4]; float4 box[4];
    float mv[4] = {m.x, m.y, m.z, m.w};
    int   mic[4] = {mi0, mi1, mi2, mi3};
    float ctv[4] = {ctr.x, ctr.y, ctr.z, ctr.w};
    float dlv[4] = {dl.x, dl.y, dl.z, dl.w};
    float dtv[4] = {dt.x, dt.y, dt.z, dt.w};
    float drv[4] = {dr.x, dr.y, dr.z, dr.w};
    float dbv[4] = {db.x, db.y, db.z, db.w};
#pragma unroll
    for (int k = 0; k < 4; k++) {
        float s = sqrtf(sigmoidf_(mv[k]) * sigmoidf_(ctv[k]));
        if (!(s > THRESH_F)) s = 0.0f;
        float px = (float)(x + k) * (float)stride + 0.5f * (float)stride;
        float x1 = fminf(fmaxf(px - dlv[k], 0.0f), IMG_W_F);
        float y1 = fminf(fmaxf(py - dtv[k], 0.0f), IMG_H_F);
        float x2 = fminf(fmaxf(px + drv[k], 0.0f), IMG_W_F);
        float y2 = fminf(fmaxf(py + dbv[k], 0.0f), IMG_H_F);
        sc[k] = s; lab[k] = mic[k];
        box[k] = make_float4(x1, y1, x2, y2);
    }

    int base = n * NP + loc;
    *(float4*)&g_scores[base] = make_float4(sc[0], sc[1], sc[2], sc[3]);
    *(int4*)&g_labels[base]   = make_int4(lab[0], lab[1], lab[2], lab[3]);
    float4* bout = (float4*)&g_boxes[(size_t)base * 4];
    bout[0] = box[0]; bout[1] = box[1]; bout[2] = box[2]; bout[3] = box[3];
}

// ============ Kernel 2: fused top-K select + sort (per batch) ============
// Histogram pivot-bin select (superset of top-1000, <= CAND), bitonic sort by
// (score_bits desc, index asc). Index tie-break == lax.top_k stability.
__global__ void __launch_bounds__(1024) k_topk() {
    __shared__ int hist[HBINS];                 // 16 KB
    __shared__ unsigned long long key[CAND];    // 16 KB
    __shared__ int wt[32];
    __shared__ int wsuf[32];
    __shared__ int sB, sCnt;

    int n = blockIdx.x;
    int tid = threadIdx.x;
    int lane = tid & 31;
    int warp = tid >> 5;
    const unsigned FULL = 0xFFFFFFFFu;

    for (int i = tid; i < HBINS; i += 1024) hist[i] = 0;
    __syncthreads();

    // pass A: linear histogram of scores (scores in [0,1))
    for (int p = tid; p < NP; p += 1024) {
        float s = g_scores[n * NP + p];
        int b = min((int)(s * (float)HBINS), HBINS - 1);
        atomicAdd(&hist[b], 1);
    }
    __syncthreads();

    // chunk sums: thread t owns bins [t*4, t*4+4)
    int b0 = tid * 4;
    int c = 0;
#pragma unroll
    for (int k = 0; k < 4; k++) c += hist[b0 + k];
    // warp inclusive suffix scan (sum over lanes >= lane)
    int x = c;
    for (int d = 1; d < 32; d <<= 1) {
        int y = __shfl_down_sync(FULL, x, d);
        if (lane + d < 32) x += y;
    }
    if (lane == 0) wt[warp] = x;    // warp total
    __syncthreads();
    if (warp == 0) {
        int t = wt[lane];
        int xx = t;
        for (int d = 1; d < 32; d <<= 1) {
            int y = __shfl_down_sync(FULL, xx, d);
            if (lane + d < 32) xx += y;
        }
        wsuf[lane] = xx - t;        // totals of warps > lane
    }
    if (tid == 0) sCnt = 0;
    __syncthreads();

    int S = wsuf[warp] + (x - c);   // count of elements in bins above this chunk
    if (S < PRE_K && S + c >= PRE_K) {   // exactly one thread
        int acc = S;
        for (int k = 3; k >= 0; k--) {
            acc += hist[b0 + k];
            if (acc >= PRE_K) { sB = b0 + k; break; }
        }
    }
    __syncthreads();
    int B = sB;

    // pass B: collect candidates with bin >= B into smem keys
    for (int p = tid; p < NP; p += 1024) {
        float s = g_scores[n * NP + p];
        int b = min((int)(s * (float)HBINS), HBINS - 1);
        if (b >= B) {
            int pos = atomicAdd(&sCnt, 1);
            if (pos < CAND)
                key[pos] = ((unsigned long long)__float_as_uint(s) << 32)
                         | (unsigned)(~(unsigned)p);
        }
    }
    __syncthreads();
    int cnt = min(sCnt, CAND);
    for (int i = cnt + tid; i < CAND; i += 1024) key[i] = 0ull;
    __syncthreads();

    // bitonic sort desc, 2048 elements, 2 per thread
    for (int k = 2; k <= CAND; k <<= 1) {
        for (int j = k >> 1; j > 0; j >>= 1) {
#pragma unroll
            for (int e = 0; e < 2; e++) {
                int idx = tid + e * 1024;
                int ixj = idx ^ j;
                if (ixj > idx) {
                    unsigned long long a = key[idx], b2 = key[ixj];
                    bool desc = (idx & k) == 0;
                    if ((a < b2) == desc) { key[idx] = b2; key[ixj] = a; }
                }
            }
            __syncthreads();
        }
    }

    // output top-1000 + valid words
    unsigned long long kk = (tid < PRE_K) ? key[tid] : 0ull;
    float s = __uint_as_float((unsigned)(kk >> 32));
    unsigned bal = __ballot_sync(FULL, (tid < PRE_K) && (s > 0.0f));
    if (lane == 0) g_validw[n * 32 + warp] = bal;
    if (tid < PRE_K) {
        int src_idx = (int)(~(unsigned)(kk & 0xFFFFFFFFull));
        int d = n * PRE_K + tid;
        g_tscore[d] = s;
        g_tlabel[d] = g_labels[n * NP + src_idx];
        *(float4*)&g_tbox[(size_t)d * 4] =
            *(const float4*)&g_boxes[((size_t)n * NP + src_idx) * 4];
    }
}

// ============ Kernel 3: suppression mask, striped rows for balance ============
// grid (NB, 8): block handles rows i = iblk + 8*t. Warp w owns j-chunk w in regs.
__global__ void k_mask() {
    __shared__ float4 sbox[1024];
    int n = blockIdx.x;
    int iblk = blockIdx.y;
    int tid = threadIdx.x;
    const unsigned FULL = 0xFFFFFFFFu;

    for (int i = tid; i < 1024; i += blockDim.x) {
        float4 b;
        if (i < PRE_K) {
            b = *(const float4*)&g_tbox[((size_t)n * PRE_K + i) * 4];
            float o = (float)g_tlabel[n * PRE_K + i] * CLS_OFF_F;
            b.x += o; b.y += o; b.z += o; b.w += o;
        } else {
            b = make_float4(0.f, 0.f, 0.f, 0.f);   // zero box -> iou = 0
        }
        sbox[i] = b;
    }
    __syncthreads();

    int w = tid >> 5;
    int lane = tid & 31;
    int j = w * 32 + lane;
    float4 jb = sbox[j];
    float ja = (jb.z - jb.x) * (jb.w - jb.y);

    int imax = w * 32 + 31;                  // rows i >= imax have no j>i in chunk
    int ilim = min(PRE_K, imax);
    int tmax = (ilim - iblk + 7) >> 3;       // i = iblk + 8t < ilim
    if (tmax < 0) tmax = 0;
    unsigned* mrow = &g_mask[(size_t)n * PRE_K * 32 + w];

#pragma unroll 2
    for (int t = 0; t < tmax; t++) {
        int i = iblk + t * 8;
        float4 ib = sbox[i];                 // broadcast, conflict-free
        float ia = (ib.z - ib.x) * (ib.w - ib.y);
        float xx1 = fmaxf(ib.x, jb.x);
        float yy1 = fmaxf(ib.y, jb.y);
        float xx2 = fminf(ib.z, jb.z);
        float yy2 = fminf(ib.w, jb.w);
        float iw = fmaxf(xx2 - xx1, 0.0f);
        float ih = fmaxf(yy2 - yy1, 0.0f);
        float inter = iw * ih;
        float iou = inter / (ia + ja - inter + 1e-9f);
        unsigned bal = __ballot_sync(FULL, iou > IOU_THR_F);
        if (lane == 0) {
            if ((i >> 5) == w) bal &= ~((2u << (i & 31)) - 1u);   // clear j <= i
            mrow[(size_t)i * 32] = bal;
        }
    }
}

// ============ Kernel 4: greedy sweep + stable partition + output ============
__global__ void k_sweep(float* out) {
    __shared__ int s_sel [POST_K];
    __shared__ int s_kept[POST_K];

    int n = blockIdx.x;
    int tid = threadIdx.x;
    int lane = tid & 31;
    const unsigned FULL = 0xFFFFFFFFu;

    if (tid < 32) {
        unsigned v = g_validw[n * 32 + lane];
        const unsigned* mb = &g_mask[(size_t)n * PRE_K * 32];

        // prefetch diagonal words: diag[W] = mask[W*32+lane][W]  (MLP=32)
        unsigned diag[32];
#pragma unroll
        for (int W = 0; W < 32; W++) {
            int i = W * 32 + lane;
            diag[W] = (i < PRE_K) ? mb[(size_t)i * 32 + W] : 0u;
        }

#pragma unroll
        for (int W = 0; W < 32; W++) {
            unsigned vw = __shfl_sync(FULL, v, W);
            unsigned sm[32];
#pragma unroll
            for (int b = 0; b < 32; b++) sm[b] = __shfl_sync(FULL, diag[W], b);
            unsigned alive = vw;
#pragma unroll
            for (int b = 0; b < 32; b++)
                if ((alive >> b) & 1u) alive &= ~sm[b];
            if (lane == W) v = alive;
            // cross-word suppression (independent loads, MLP-covered)
            unsigned rem = alive;
            while (rem) {
                int b = __ffs(rem) - 1;
                rem &= rem - 1;
                int i = W * 32 + b;
                unsigned row = (lane > W) ? mb[(size_t)i * 32 + lane] : 0u;
                v &= ~row;
            }
        }

        // stable partition (kept in index order, then dropped in index order)
        int c = __popc(v);
        int incl = c;
        for (int d = 1; d < 32; d <<= 1) {
            int t = __shfl_up_sync(FULL, incl, d);
            if (lane >= d) incl += t;
        }
        int pre = incl - c;
        int totK = __shfl_sync(FULL, incl, 31);
        for (int b = 0; b < 32; b++) {
            int i = lane * 32 + b;
            if (i >= PRE_K) break;
            bool kept = (v >> b) & 1u;
            int kb = pre + __popc(v & ((1u << b) - 1u));
            int pos = kept ? kb : (totK + (i - kb));
            if (pos < POST_K) { s_sel[pos] = i; s_kept[pos] = kept ? 1 : 0; }
        }
    }
    __syncthreads();

    if (tid < POST_K) {
        int i = s_sel[tid];
        int kept = s_kept[tid];
        int src = n * PRE_K + i;
        int dst = n * POST_K + tid;
        float4 b = *(const float4*)&g_tbox[(size_t)src * 4];
        ((float4*)out)[dst] = b;
        out[NB * POST_K * 4 + dst] = kept ? g_tscore[src] : 0.0f;          // scores
        out[NB * POST_K * 4 + NB * POST_K + dst] = (float)g_tlabel[src];   // labels
    }
}

// ---------------- host launch ----------------
extern "C" void kernel_launch(void* const* d_in, const int* in_sizes, int n_in,
                              void* d_out, int out_size) {
    (void)in_sizes; (void)n_in; (void)out_size;

    Ptrs p;
    for (int l = 0; l < 5; l++) {
        p.cls[l] = (const float*)d_in[3 * l + 0];
        p.reg[l] = (const float*)d_in[3 * l + 1];
        p.ctr[l] = (const float*)d_in[3 * l + 2];
    }
    float* out = (float*)d_out;

    int total = NB * NP4;
    k_decode<<<(total + 255) / 256, 256>>>(p);
    k_topk<<<NB, 1024>>>();
    k_mask<<<dim3(NB, 8), 1024>>>();
    k_sweep<<<NB, 128>>>(out);
}

// round 8
// speedup vs baseline: 3.9916x; 1.6063x over previous
#include <cuda_runtime.h>
#include <cuda_bf16.h>
#include <cstdint>

// ---------------- problem constants ----------------
#define NB 16        // batch
#define NC 80        // classes
#define NP 17064     // total locations across 5 levels
#define NP4 (NP / 4) // 4266
#define PRE_K 1000
#define POST_K 100
#define CAND 2048
#define HBINS 4096
#define IMG_W_F 1024.0f
#define IMG_H_F 800.0f
#define THRESH_F 0.05f
#define IOU_THR_F 0.6f
#define CLS_OFF_F 4096.0f

struct Ptrs {
    const float* cls[5];
    const float* reg[5];
    const float* ctr[5];
};

// ---------------- device scratch (static, no allocs; zero-initialized) ----------------
__device__ float    g_scores[NB * NP];
__device__ int      g_labels[NB * NP];
__device__ float    g_boxes [NB * NP * 4];
__device__ float    g_tscore[NB * PRE_K];
__device__ int      g_tlabel[NB * PRE_K];
__device__ float    g_tbox  [NB * PRE_K * 4];
__device__ unsigned g_mask  [NB * PRE_K * 32];   // unwritten words stay 0 (no j>i bits there)
__device__ unsigned g_validw[NB * 32];

__device__ __forceinline__ float sigmoidf_(float x) {
    return 1.0f / (1.0f + expf(-x));
}

// ============ Kernel 1: decode, 4 consecutive locations per thread ============
__global__ void k_decode(Ptrs p) {
    int gid = blockIdx.x * blockDim.x + threadIdx.x;
    if (gid >= NB * NP4) return;
    int n = gid / NP4;
    int loc = (gid - n * NP4) * 4;

    int l, off, ww, stride, hw;
    if (loc < 12800)      { l = 0; off = 0;     ww = 128; stride = 8;   hw = 12800; }
    else if (loc < 16000) { l = 1; off = 12800; ww = 64;  stride = 16;  hw = 3200;  }
    else if (loc < 16800) { l = 2; off = 16000; ww = 32;  stride = 32;  hw = 800;   }
    else if (loc < 17008) { l = 3; off = 16800; ww = 16;  stride = 64;  hw = 208;   }
    else                  { l = 4; off = 17008; ww = 8;   stride = 128; hw = 56;    }

    int local = loc - off;               // multiple of 4; ww % 4 == 0 -> same row
    int y = local / ww;
    int x = local - y * ww;

    // argmax over class logits for 4 locations (sigmoid monotone)
    const float4* cls = (const float4*)(p.cls[l] + (size_t)n * NC * hw + local);
    size_t cstride = (size_t)hw / 4;     // float4 stride between classes
    float4 m = __ldg(&cls[0]);
    int mi0 = 0, mi1 = 0, mi2 = 0, mi3 = 0;
#pragma unroll 16
    for (int c = 1; c < NC; c++) {
        float4 v = __ldg(&cls[(size_t)c * cstride]);
        if (v.x > m.x) { m.x = v.x; mi0 = c; }
        if (v.y > m.y) { m.y = v.y; mi1 = c; }
        if (v.z > m.z) { m.z = v.z; mi2 = c; }
        if (v.w > m.w) { m.w = v.w; mi3 = c; }
    }

    float4 ctr = __ldg((const float4*)(p.ctr[l] + (size_t)n * hw + local));
    const float* reg = p.reg[l] + (size_t)n * 4 * hw + local;
    float4 dl = __ldg((const float4*)(reg));
    float4 dt = __ldg((const float4*)(reg + hw));
    float4 dr = __ldg((const float4*)(reg + 2 * hw));
    float4 db = __ldg((const float4*)(reg + 3 * hw));

    float py = (float)y * (float)stride + 0.5f * (float)stride;
    float sc[4]; int lab[4]; float4 box[4];
    float mv[4] = {m.x, m.y, m.z, m.w};
    int   mic[4] = {mi0, mi1, mi2, mi3};
    float ctv[4] = {ctr.x, ctr.y, ctr.z, ctr.w};
    float dlv[4] = {dl.x, dl.y, dl.z, dl.w};
    float dtv[4] = {dt.x, dt.y, dt.z, dt.w};
    float drv[4] = {dr.x, dr.y, dr.z, dr.w};
    float dbv[4] = {db.x, db.y, db.z, db.w};
#pragma unroll
    for (int k = 0; k < 4; k++) {
        float s = sqrtf(sigmoidf_(mv[k]) * sigmoidf_(ctv[k]));
        if (!(s > THRESH_F)) s = 0.0f;
        float px = (float)(x + k) * (float)stride + 0.5f * (float)stride;
        float x1 = fminf(fmaxf(px - dlv[k], 0.0f), IMG_W_F);
        float y1 = fminf(fmaxf(py - dtv[k], 0.0f), IMG_H_F);
        float x2 = fminf(fmaxf(px + drv[k], 0.0f), IMG_W_F);
        float y2 = fminf(fmaxf(py + dbv[k], 0.0f), IMG_H_F);
        sc[k] = s; lab[k] = mic[k];
        box[k] = make_float4(x1, y1, x2, y2);
    }

    int base = n * NP + loc;
    *(float4*)&g_scores[base] = make_float4(sc[0], sc[1], sc[2], sc[3]);
    *(int4*)&g_labels[base]   = make_int4(lab[0], lab[1], lab[2], lab[3]);
    float4* bout = (float4*)&g_boxes[(size_t)base * 4];
    bout[0] = box[0]; bout[1] = box[1]; bout[2] = box[2]; bout[3] = box[3];
}

// ============ Kernel 2: fused top-K select + sort (per batch) ============
// Histogram pivot-bin select (superset of top-1000, <= CAND), bitonic sort by
// (score_bits desc, index asc). Index tie-break == lax.top_k stability.
__global__ void __launch_bounds__(1024) k_topk() {
    __shared__ int hist[HBINS];                 // 16 KB
    __shared__ unsigned long long key[CAND];    // 16 KB
    __shared__ int wt[32];
    __shared__ int wsuf[32];
    __shared__ int sB, sCnt;

    int n = blockIdx.x;
    int tid = threadIdx.x;
    int lane = tid & 31;
    int warp = tid >> 5;
    const unsigned FULL = 0xFFFFFFFFu;

    for (int i = tid; i < HBINS; i += 1024) hist[i] = 0;
    __syncthreads();

    // pass A: linear histogram of scores (scores in [0,1))
    for (int p = tid; p < NP; p += 1024) {
        float s = g_scores[n * NP + p];
        int b = min((int)(s * (float)HBINS), HBINS - 1);
        atomicAdd(&hist[b], 1);
    }
    __syncthreads();

    // chunk sums: thread t owns bins [t*4, t*4+4)
    int b0 = tid * 4;
    int c = 0;
#pragma unroll
    for (int k = 0; k < 4; k++) c += hist[b0 + k];
    // warp inclusive suffix scan (sum over lanes >= lane)
    int x = c;
    for (int d = 1; d < 32; d <<= 1) {
        int y = __shfl_down_sync(FULL, x, d);
        if (lane + d < 32) x += y;
    }
    if (lane == 0) wt[warp] = x;    // warp total
    __syncthreads();
    if (warp == 0) {
        int t = wt[lane];
        int xx = t;
        for (int d = 1; d < 32; d <<= 1) {
            int y = __shfl_down_sync(FULL, xx, d);
            if (lane + d < 32) xx += y;
        }
        wsuf[lane] = xx - t;        // totals of warps > lane
    }
    if (tid == 0) sCnt = 0;
    __syncthreads();

    int S = wsuf[warp] + (x - c);   // count of elements in bins above this chunk
    if (S < PRE_K && S + c >= PRE_K) {   // exactly one thread
        int acc = S;
        for (int k = 3; k >= 0; k--) {
            acc += hist[b0 + k];
            if (acc >= PRE_K) { sB = b0 + k; break; }
        }
    }
    __syncthreads();
    int B = sB;

    // pass B: collect candidates with bin >= B into smem keys
    for (int p = tid; p < NP; p += 1024) {
        float s = g_scores[n * NP + p];
        int b = min((int)(s * (float)HBINS), HBINS - 1);
        if (b >= B) {
            int pos = atomicAdd(&sCnt, 1);
            if (pos < CAND)
                key[pos] = ((unsigned long long)__float_as_uint(s) << 32)
                         | (unsigned)(~(unsigned)p);
        }
    }
    __syncthreads();
    int cnt = min(sCnt, CAND);
    for (int i = cnt + tid; i < CAND; i += 1024) key[i] = 0ull;
    __syncthreads();

    // bitonic sort desc, 2048 elements, 2 per thread
    for (int k = 2; k <= CAND; k <<= 1) {
        for (int j = k >> 1; j > 0; j >>= 1) {
#pragma unroll
            for (int e = 0; e < 2; e++) {
                int idx = tid + e * 1024;
                int ixj = idx ^ j;
                if (ixj > idx) {
                    unsigned long long a = key[idx], b2 = key[ixj];
                    bool desc = (idx & k) == 0;
                    if ((a < b2) == desc) { key[idx] = b2; key[ixj] = a; }
                }
            }
            __syncthreads();
        }
    }

    // output top-1000 + valid words
    unsigned long long kk = (tid < PRE_K) ? key[tid] : 0ull;
    float s = __uint_as_float((unsigned)(kk >> 32));
    unsigned bal = __ballot_sync(FULL, (tid < PRE_K) && (s > 0.0f));
    if (lane == 0) g_validw[n * 32 + warp] = bal;
    if (tid < PRE_K) {
        int src_idx = (int)(~(unsigned)(kk & 0xFFFFFFFFull));
        int d = n * PRE_K + tid;
        g_tscore[d] = s;
        g_tlabel[d] = g_labels[n * NP + src_idx];
        *(float4*)&g_tbox[(size_t)d * 4] =
            *(const float4*)&g_boxes[((size_t)n * NP + src_idx) * 4];
    }
}

// ============ Kernel 3: suppression mask, striped rows for balance ============
// grid (NB, 8): block handles rows i = iblk + 8*t. Warp w owns j-chunk w in regs.
__global__ void k_mask() {
    __shared__ float4 sbox[1024];
    int n = blockIdx.x;
    int iblk = blockIdx.y;
    int tid = threadIdx.x;
    const unsigned FULL = 0xFFFFFFFFu;

    for (int i = tid; i < 1024; i += blockDim.x) {
        float4 b;
        if (i < PRE_K) {
            b = *(const float4*)&g_tbox[((size_t)n * PRE_K + i) * 4];
            float o = (float)g_tlabel[n * PRE_K + i] * CLS_OFF_F;
            b.x += o; b.y += o; b.z += o; b.w += o;
        } else {
            b = make_float4(0.f, 0.f, 0.f, 0.f);   // zero box -> iou = 0
        }
        sbox[i] = b;
    }
    __syncthreads();

    int w = tid >> 5;
    int lane = tid & 31;
    int j = w * 32 + lane;
    float4 jb = sbox[j];
    float ja = (jb.z - jb.x) * (jb.w - jb.y);

    int imax = w * 32 + 31;                  // rows i >= imax have no j>i in chunk
    int ilim = min(PRE_K, imax);
    int tmax = (ilim - iblk + 7) >> 3;       // i = iblk + 8t < ilim
    if (tmax < 0) tmax = 0;
    unsigned* mrow = &g_mask[(size_t)n * PRE_K * 32 + w];

#pragma unroll 2
    for (int t = 0; t < tmax; t++) {
        int i = iblk + t * 8;
        float4 ib = sbox[i];                 // broadcast, conflict-free
        float ia = (ib.z - ib.x) * (ib.w - ib.y);
        float xx1 = fmaxf(ib.x, jb.x);
        float yy1 = fmaxf(ib.y, jb.y);
        float xx2 = fminf(ib.z, jb.z);
        float yy2 = fminf(ib.w, jb.w);
        float iw = fmaxf(xx2 - xx1, 0.0f);
        float ih = fmaxf(yy2 - yy1, 0.0f);
        float inter = iw * ih;
        float iou = inter / (ia + ja - inter + 1e-9f);
        unsigned bal = __ballot_sync(FULL, iou > IOU_THR_F);
        if (lane == 0) {
            if ((i >> 5) == w) bal &= ~((2u << (i & 31)) - 1u);   // clear j <= i
            mrow[(size_t)i * 32] = bal;
        }
    }
}

// ============ Kernel 4: greedy sweep (register-tile prefetch) + output ============
__global__ void k_sweep(float* out) {
    __shared__ int s_sel [POST_K];
    __shared__ int s_kept[POST_K];

    int n = blockIdx.x;
    int tid = threadIdx.x;
    int lane = tid & 31;
    const unsigned FULL = 0xFFFFFFFFu;

    if (tid < 32) {
        unsigned v = g_validw[n * 32 + lane];
        const unsigned* mb = &g_mask[(size_t)n * PRE_K * 32];

#pragma unroll 1
        for (int W = 0; W < 32; W++) {
            unsigned vw = __shfl_sync(FULL, v, W);
            if (vw == 0) continue;            // warp-uniform skip

            // prefetch transpose tile: rows[b] = mask[W*32+b][lane], MLP=32
            unsigned rows[32];
            const unsigned* base = mb + (size_t)(W * 32) * 32 + lane;
#pragma unroll
            for (int b = 0; b < 32; b++) {
                int i = W * 32 + b;
                rows[b] = (i < PRE_K) ? base[b * 32] : 0u;
            }

            // within-word greedy closure: lane W's rows[] column IS the diagonal word
            unsigned alive = vw;
#pragma unroll
            for (int b = 0; b < 32; b++)
                if ((alive >> b) & 1u) alive &= ~rows[b];
            alive = __shfl_sync(FULL, alive, W);     // only lane W's value is correct
            if (lane == W) v = alive;

            // cross-word suppression, pure register ANDs
            // (lanes < W hold zero words; lane W idempotent)
            unsigned rem = alive;
            while (rem) {
                int b = __ffs(rem) - 1;
                rem &= rem - 1;
                v &= ~rows[b];
            }
        }

        // stable partition (kept in index order, then dropped in index order)
        int c = __popc(v);
        int incl = c;
        for (int d = 1; d < 32; d <<= 1) {
            int t = __shfl_up_sync(FULL, incl, d);
            if (lane >= d) incl += t;
        }
        int pre = incl - c;
        int totK = __shfl_sync(FULL, incl, 31);
        for (int b = 0; b < 32; b++) {
            int i = lane * 32 + b;
            if (i >= PRE_K) break;
            bool kept = (v >> b) & 1u;
            int kb = pre + __popc(v & ((1u << b) - 1u));
            int pos = kept ? kb : (totK + (i - kb));
            if (pos < POST_K) { s_sel[pos] = i; s_kept[pos] = kept ? 1 : 0; }
        }
    }
    __syncthreads();

    if (tid < POST_K) {
        int i = s_sel[tid];
        int kept = s_kept[tid];
        int src = n * PRE_K + i;
        int dst = n * POST_K + tid;
        float4 b = *(const float4*)&g_tbox[(size_t)src * 4];
        ((float4*)out)[dst] = b;
        out[NB * POST_K * 4 + dst] = kept ? g_tscore[src] : 0.0f;          // scores
        out[NB * POST_K * 4 + NB * POST_K + dst] = (float)g_tlabel[src];   // labels
    }
}

// ---------------- host launch ----------------
extern "C" void kernel_launch(void* const* d_in, const int* in_sizes, int n_in,
                              void* d_out, int out_size) {
    (void)in_sizes; (void)n_in; (void)out_size;

    Ptrs p;
    for (int l = 0; l < 5; l++) {
        p.cls[l] = (const float*)d_in[3 * l + 0];
        p.reg[l] = (const float*)d_in[3 * l + 1];
        p.ctr[l] = (const float*)d_in[3 * l + 2];
    }
    float* out = (float*)d_out;

    int total = NB * NP4;
    k_decode<<<(total + 255) / 256, 256>>>(p);
    k_topk<<<NB, 1024>>>();
    k_mask<<<dim3(NB, 8), 1024>>>();
    k_sweep<<<NB, 128>>>(out);
}

// round 9
// speedup vs baseline: 5.3541x; 1.3413x over previous
#include <cuda_runtime.h>
#include <cuda_bf16.h>
#include <cstdint>

// ---------------- problem constants ----------------
#define NB 16        // batch
#define NC 80        // classes
#define NP 17064     // total locations across 5 levels
#define NP4 (NP / 4) // 4266
#define PRE_K 1000
#define POST_K 100
#define CAND 2048
#define HBINS 4096
#define IMG_W_F 1024.0f
#define IMG_H_F 800.0f
#define THRESH_F 0.05f
#define IOU_THR_F 0.6f
#define CLS_OFF_F 4096.0f

struct Ptrs {
    const float* cls[5];
    const float* reg[5];
    const float* ctr[5];
};

// ---------------- device scratch (static, no allocs; zero-initialized) ----------------
__device__ float    g_scores[NB * NP];
__device__ int      g_labels[NB * NP];
__device__ float    g_boxes [NB * NP * 4];
__device__ float    g_tscore[NB * PRE_K];
__device__ int      g_tlabel[NB * PRE_K];
__device__ float    g_tbox  [NB * PRE_K * 4];
__device__ unsigned g_mask  [NB * PRE_K * 32];   // unwritten words stay 0 (no j>i bits there)
__device__ unsigned g_validw[NB * 32];

__device__ __forceinline__ float sigmoidf_(float x) {
    return 1.0f / (1.0f + expf(-x));
}

// ============ Kernel 1: decode, 4 consecutive locations per thread ============
__global__ void k_decode(Ptrs p) {
    int gid = blockIdx.x * blockDim.x + threadIdx.x;
    if (gid >= NB * NP4) return;
    int n = gid / NP4;
    int loc = (gid - n * NP4) * 4;

    int l, off, ww, stride, hw;
    if (loc < 12800)      { l = 0; off = 0;     ww = 128; stride = 8;   hw = 12800; }
    else if (loc < 16000) { l = 1; off = 12800; ww = 64;  stride = 16;  hw = 3200;  }
    else if (loc < 16800) { l = 2; off = 16000; ww = 32;  stride = 32;  hw = 800;   }
    else if (loc < 17008) { l = 3; off = 16800; ww = 16;  stride = 64;  hw = 208;   }
    else                  { l = 4; off = 17008; ww = 8;   stride = 128; hw = 56;    }

    int local = loc - off;               // multiple of 4; ww % 4 == 0 -> same row
    int y = local / ww;
    int x = local - y * ww;

    // argmax over class logits for 4 locations (sigmoid monotone)
    const float4* cls = (const float4*)(p.cls[l] + (size_t)n * NC * hw + local);
    size_t cstride = (size_t)hw / 4;     // float4 stride between classes
    float4 m = __ldg(&cls[0]);
    int mi0 = 0, mi1 = 0, mi2 = 0, mi3 = 0;
#pragma unroll 16
    for (int c = 1; c < NC; c++) {
        float4 v = __ldg(&cls[(size_t)c * cstride]);
        if (v.x > m.x) { m.x = v.x; mi0 = c; }
        if (v.y > m.y) { m.y = v.y; mi1 = c; }
        if (v.z > m.z) { m.z = v.z; mi2 = c; }
        if (v.w > m.w) { m.w = v.w; mi3 = c; }
    }

    float4 ctr = __ldg((const float4*)(p.ctr[l] + (size_t)n * hw + local));
    const float* reg = p.reg[l] + (size_t)n * 4 * hw + local;
    float4 dl = __ldg((const float4*)(reg));
    float4 dt = __ldg((const float4*)(reg + hw));
    float4 dr = __ldg((const float4*)(reg + 2 * hw));
    float4 db = __ldg((const float4*)(reg + 3 * hw));

    float py = (float)y * (float)stride + 0.5f * (float)stride;
    float sc[4]; int lab[4]; float4 box[4];
    float mv[4] = {m.x, m.y, m.z, m.w};
    int   mic[4] = {mi0, mi1, mi2, mi3};
    float ctv[4] = {ctr.x, ctr.y, ctr.z, ctr.w};
    float dlv[4] = {dl.x, dl.y, dl.z, dl.w};
    float dtv[4] = {dt.x, dt.y, dt.z, dt.w};
    float drv[4] = {dr.x, dr.y, dr.z, dr.w};
    float dbv[4] = {db.x, db.y, db.z, db.w};
#pragma unroll
    for (int k = 0; k < 4; k++) {
        float s = sqrtf(sigmoidf_(mv[k]) * sigmoidf_(ctv[k]));
        if (!(s > THRESH_F)) s = 0.0f;
        float px = (float)(x + k) * (float)stride + 0.5f * (float)stride;
        float x1 = fminf(fmaxf(px - dlv[k], 0.0f), IMG_W_F);
        float y1 = fminf(fmaxf(py - dtv[k], 0.0f), IMG_H_F);
        float x2 = fminf(fmaxf(px + drv[k], 0.0f), IMG_W_F);
        float y2 = fminf(fmaxf(py + dbv[k], 0.0f), IMG_H_F);
        sc[k] = s; lab[k] = mic[k];
        box[k] = make_float4(x1, y1, x2, y2);
    }

    int base = n * NP + loc;
    *(float4*)&g_scores[base] = make_float4(sc[0], sc[1], sc[2], sc[3]);
    *(int4*)&g_labels[base]   = make_int4(lab[0], lab[1], lab[2], lab[3]);
    float4* bout = (float4*)&g_boxes[(size_t)base * 4];
    bout[0] = box[0]; bout[1] = box[1]; bout[2] = box[2]; bout[3] = box[3];
}

// ============ Kernel 2: fused top-K select + sort (per batch) ============
// Histogram pivot-bin select (superset of top-1000, <= CAND), bitonic sort by
// (score_bits desc, index asc). Index tie-break == lax.top_k stability.
__global__ void __launch_bounds__(1024) k_topk() {
    __shared__ int hist[HBINS];                 // 16 KB
    __shared__ unsigned long long key[CAND];    // 16 KB
    __shared__ int wt[32];
    __shared__ int wsuf[32];
    __shared__ int sB, sCnt;

    int n = blockIdx.x;
    int tid = threadIdx.x;
    int lane = tid & 31;
    int warp = tid >> 5;
    const unsigned FULL = 0xFFFFFFFFu;

    for (int i = tid; i < HBINS; i += 1024) hist[i] = 0;
    __syncthreads();

    // pass A: linear histogram of scores (scores in [0,1))
    for (int p = tid; p < NP; p += 1024) {
        float s = g_scores[n * NP + p];
        int b = min((int)(s * (float)HBINS), HBINS - 1);
        atomicAdd(&hist[b], 1);
    }
    __syncthreads();

    // chunk sums: thread t owns bins [t*4, t*4+4)
    int b0 = tid * 4;
    int c = 0;
#pragma unroll
    for (int k = 0; k < 4; k++) c += hist[b0 + k];
    // warp inclusive suffix scan (sum over lanes >= lane)
    int x = c;
    for (int d = 1; d < 32; d <<= 1) {
        int y = __shfl_down_sync(FULL, x, d);
        if (lane + d < 32) x += y;
    }
    if (lane == 0) wt[warp] = x;    // warp total
    __syncthreads();
    if (warp == 0) {
        int t = wt[lane];
        int xx = t;
        for (int d = 1; d < 32; d <<= 1) {
            int y = __shfl_down_sync(FULL, xx, d);
            if (lane + d < 32) xx += y;
        }
        wsuf[lane] = xx - t;        // totals of warps > lane
    }
    if (tid == 0) sCnt = 0;
    __syncthreads();

    int S = wsuf[warp] + (x - c);   // count of elements in bins above this chunk
    if (S < PRE_K && S + c >= PRE_K) {   // exactly one thread
        int acc = S;
        for (int k = 3; k >= 0; k--) {
            acc += hist[b0 + k];
            if (acc >= PRE_K) { sB = b0 + k; break; }
        }
    }
    __syncthreads();
    int B = sB;

    // pass B: collect candidates with bin >= B into smem keys
    for (int p = tid; p < NP; p += 1024) {
        float s = g_scores[n * NP + p];
        int b = min((int)(s * (float)HBINS), HBINS - 1);
        if (b >= B) {
            int pos = atomicAdd(&sCnt, 1);
            if (pos < CAND)
                key[pos] = ((unsigned long long)__float_as_uint(s) << 32)
                         | (unsigned)(~(unsigned)p);
        }
    }
    __syncthreads();
    int cnt = min(sCnt, CAND);
    for (int i = cnt + tid; i < CAND; i += 1024) key[i] = 0ull;
    __syncthreads();

    // bitonic sort desc, 2048 elements, 2 per thread
    for (int k = 2; k <= CAND; k <<= 1) {
        for (int j = k >> 1; j > 0; j >>= 1) {
#pragma unroll
            for (int e = 0; e < 2; e++) {
                int idx = tid + e * 1024;
                int ixj = idx ^ j;
                if (ixj > idx) {
                    unsigned long long a = key[idx], b2 = key[ixj];
                    bool desc = (idx & k) == 0;
                    if ((a < b2) == desc) { key[idx] = b2; key[ixj] = a; }
                }
            }
            __syncthreads();
        }
    }

    // output top-1000 + valid words
    unsigned long long kk = (tid < PRE_K) ? key[tid] : 0ull;
    float s = __uint_as_float((unsigned)(kk >> 32));
    unsigned bal = __ballot_sync(FULL, (tid < PRE_K) && (s > 0.0f));
    if (lane == 0) g_validw[n * 32 + warp] = bal;
    if (tid < PRE_K) {
        int src_idx = (int)(~(unsigned)(kk & 0xFFFFFFFFull));
        int d = n * PRE_K + tid;
        g_tscore[d] = s;
        g_tlabel[d] = g_labels[n * NP + src_idx];
        *(float4*)&g_tbox[(size_t)d * 4] =
            *(const float4*)&g_boxes[((size_t)n * NP + src_idx) * 4];
    }
}

// ============ Kernel 3: suppression mask, striped rows for balance ============
// grid (NB, 8): block handles rows i = iblk + 8*t. Warp w owns j-chunk w in regs.
__global__ void k_mask() {
    __shared__ float4 sbox[1024];
    int n = blockIdx.x;
    int iblk = blockIdx.y;
    int tid = threadIdx.x;
    const unsigned FULL = 0xFFFFFFFFu;

    for (int i = tid; i < 1024; i += blockDim.x) {
        float4 b;
        if (i < PRE_K) {
            b = *(const float4*)&g_tbox[((size_t)n * PRE_K + i) * 4];
            float o = (float)g_tlabel[n * PRE_K + i] * CLS_OFF_F;
            b.x += o; b.y += o; b.z += o; b.w += o;
        } else {
            b = make_float4(0.f, 0.f, 0.f, 0.f);   // zero box -> iou = 0
        }
        sbox[i] = b;
    }
    __syncthreads();

    int w = tid >> 5;
    int lane = tid & 31;
    int j = w * 32 + lane;
    float4 jb = sbox[j];
    float ja = (jb.z - jb.x) * (jb.w - jb.y);

    int imax = w * 32 + 31;                  // rows i >= imax have no j>i in chunk
    int ilim = min(PRE_K, imax);
    int tmax = (ilim - iblk + 7) >> 3;       // i = iblk + 8t < ilim
    if (tmax < 0) tmax = 0;
    unsigned* mrow = &g_mask[(size_t)n * PRE_K * 32 + w];

#pragma unroll 2
    for (int t = 0; t < tmax; t++) {
        int i = iblk + t * 8;
        float4 ib = sbox[i];                 // broadcast, conflict-free
        float ia = (ib.z - ib.x) * (ib.w - ib.y);
        float xx1 = fmaxf(ib.x, jb.x);
        float yy1 = fmaxf(ib.y, jb.y);
        float xx2 = fminf(ib.z, jb.z);
        float yy2 = fminf(ib.w, jb.w);
        float iw = fmaxf(xx2 - xx1, 0.0f);
        float ih = fmaxf(yy2 - yy1, 0.0f);
        float inter = iw * ih;
        float iou = inter / (ia + ja - inter + 1e-9f);
        unsigned bal = __ballot_sync(FULL, iou > IOU_THR_F);
        if (lane == 0) {
            if ((i >> 5) == w) bal &= ~((2u << (i & 31)) - 1u);   // clear j <= i
            mrow[(size_t)i * 32] = bal;
        }
    }
}

// ============ Kernel 4: greedy sweep (static register tile) + output ============
__global__ void k_sweep(float* out) {
    __shared__ int s_sel [POST_K];
    __shared__ int s_kept[POST_K];

    int n = blockIdx.x;
    int tid = threadIdx.x;
    int lane = tid & 31;
    const unsigned FULL = 0xFFFFFFFFu;

    if (tid < 32) {
        unsigned v = g_validw[n * 32 + lane];
        const unsigned* mb = &g_mask[(size_t)n * PRE_K * 32];

#pragma unroll 1
        for (int W = 0; W < 32; W++) {
            unsigned vw = __shfl_sync(FULL, v, W);
            if (vw == 0) continue;            // warp-uniform skip

            // prefetch transpose tile: rows[b] = mask[W*32+b][lane]
            // ALL accesses statically indexed -> stays in registers, MLP=32
            unsigned rows[32];
            const unsigned* base = mb + (size_t)(W * 32) * 32 + lane;
#pragma unroll
            for (int b = 0; b < 32; b++) {
                int i = W * 32 + b;
                rows[b] = (i < PRE_K) ? base[b * 32] : 0u;
            }

            // within-word greedy closure: lane W's rows[] column IS the diagonal word
            unsigned alive = vw;
#pragma unroll
            for (int b = 0; b < 32; b++)
                if ((alive >> b) & 1u) alive &= ~rows[b];
            alive = __shfl_sync(FULL, alive, W);     // only lane W's value is correct
            if (lane == W) v = alive;

            // cross-word suppression: static-indexed predicated ANDs
            // (lanes < W hold zero words; lane W idempotent)
#pragma unroll
            for (int b = 0; b < 32; b++)
                if ((alive >> b) & 1u) v &= ~rows[b];
        }

        // stable partition (kept in index order, then dropped in index order)
        int c = __popc(v);
        int incl = c;
        for (int d = 1; d < 32; d <<= 1) {
            int t = __shfl_up_sync(FULL, incl, d);
            if (lane >= d) incl += t;
        }
        int pre = incl - c;
        int totK = __shfl_sync(FULL, incl, 31);
        for (int b = 0; b < 32; b++) {
            int i = lane * 32 + b;
            if (i >= PRE_K) break;
            bool kept = (v >> b) & 1u;
            int kb = pre + __popc(v & ((1u << b) - 1u));
            int pos = kept ? kb : (totK + (i - kb));
            if (pos < POST_K) { s_sel[pos] = i; s_kept[pos] = kept ? 1 : 0; }
        }
    }
    __syncthreads();

    if (tid < POST_K) {
        int i = s_sel[tid];
        int kept = s_kept[tid];
        int src = n * PRE_K + i;
        int dst = n * POST_K + tid;
        float4 b = *(const float4*)&g_tbox[(size_t)src * 4];
        ((float4*)out)[dst] = b;
        out[NB * POST_K * 4 + dst] = kept ? g_tscore[src] : 0.0f;          // scores
        out[NB * POST_K * 4 + NB * POST_K + dst] = (float)g_tlabel[src];   // labels
    }
}

// ---------------- host launch ----------------
extern "C" void kernel_launch(void* const* d_in, const int* in_sizes, int n_in,
                              void* d_out, int out_size) {
    (void)in_sizes; (void)n_in; (void)out_size;

    Ptrs p;
    for (int l = 0; l < 5; l++) {
        p.cls[l] = (const float*)d_in[3 * l + 0];
        p.reg[l] = (const float*)d_in[3 * l + 1];
        p.ctr[l] = (const float*)d_in[3 * l + 2];
    }
    float* out = (float*)d_out;

    int total = NB * NP4;
    k_decode<<<(total + 255) / 256, 256>>>(p);
    k_topk<<<NB, 1024>>>();
    k_mask<<<dim3(NB, 8), 1024>>>();
    k_sweep<<<NB, 128>>>(out);
}

// round 10
// speedup vs baseline: 5.5227x; 1.0315x over previous
#include <cuda_runtime.h>
#include <cuda_bf16.h>
#include <cstdint>

// ---------------- problem constants ----------------
#define NB 16        // batch
#define NC 80        // classes
#define NP 17064     // total locations across 5 levels
#define NP4 (NP / 4) // 4266
#define PRE_K 1000
#define POST_K 100
#define CAND 2048
#define HBINS 4096
#define IMG_W_F 1024.0f
#define IMG_H_F 800.0f
#define THRESH_F 0.05f
#define IOU_THR_F 0.6f
#define CLS_OFF_F 4096.0f

struct Ptrs {
    const float* cls[5];
    const float* reg[5];
    const float* ctr[5];
};

// ---------------- device scratch (static, no allocs; zero-initialized) ----------------
__device__ float    g_scores[NB * NP];
__device__ int      g_labels[NB * NP];
__device__ float    g_boxes [NB * NP * 4];
__device__ float    g_tscore[NB * PRE_K];
__device__ int      g_tlabel[NB * PRE_K];
__device__ float    g_tbox  [NB * PRE_K * 4];
// transposed mask: g_maskT[(n*32 + w) * 1024 + i] = suppression word of j-chunk w by box i.
// rows i in [ilim,1024) never written by any run -> stay zero (triangular invariant).
__device__ unsigned g_maskT [NB * 32 * 1024];
__device__ unsigned g_validw[NB * 32];

__device__ __forceinline__ float sigmoidf_(float x) {
    return 1.0f / (1.0f + expf(-x));
}

// ============ Kernel 1: decode, 4 consecutive locations per thread ============
__global__ void k_decode(Ptrs p) {
    int gid = blockIdx.x * blockDim.x + threadIdx.x;
    if (gid >= NB * NP4) return;
    int n = gid / NP4;
    int loc = (gid - n * NP4) * 4;

    int l, off, ww, stride, hw;
    if (loc < 12800)      { l = 0; off = 0;     ww = 128; stride = 8;   hw = 12800; }
    else if (loc < 16000) { l = 1; off = 12800; ww = 64;  stride = 16;  hw = 3200;  }
    else if (loc < 16800) { l = 2; off = 16000; ww = 32;  stride = 32;  hw = 800;   }
    else if (loc < 17008) { l = 3; off = 16800; ww = 16;  stride = 64;  hw = 208;   }
    else                  { l = 4; off = 17008; ww = 8;   stride = 128; hw = 56;    }

    int local = loc - off;               // multiple of 4; ww % 4 == 0 -> same row
    int y = local / ww;
    int x = local - y * ww;

    // argmax over class logits for 4 locations (sigmoid monotone)
    const float4* cls = (const float4*)(p.cls[l] + (size_t)n * NC * hw + local);
    size_t cstride = (size_t)hw / 4;     // float4 stride between classes
    float4 m = __ldg(&cls[0]);
    int mi0 = 0, mi1 = 0, mi2 = 0, mi3 = 0;
#pragma unroll 16
    for (int c = 1; c < NC; c++) {
        float4 v = __ldg(&cls[(size_t)c * cstride]);
        if (v.x > m.x) { m.x = v.x; mi0 = c; }
        if (v.y > m.y) { m.y = v.y; mi1 = c; }
        if (v.z > m.z) { m.z = v.z; mi2 = c; }
        if (v.w > m.w) { m.w = v.w; mi3 = c; }
    }

    float4 ctr = __ldg((const float4*)(p.ctr[l] + (size_t)n * hw + local));
    const float* reg = p.reg[l] + (size_t)n * 4 * hw + local;
    float4 dl = __ldg((const float4*)(reg));
    float4 dt = __ldg((const float4*)(reg + hw));
    float4 dr = __ldg((const float4*)(reg + 2 * hw));
    float4 db = __ldg((const float4*)(reg + 3 * hw));

    float py = (float)y * (float)stride + 0.5f * (float)stride;
    float sc[4]; int lab[4]; float4 box[4];
    float mv[4] = {m.x, m.y, m.z, m.w};
    int   mic[4] = {mi0, mi1, mi2, mi3};
    float ctv[4] = {ctr.x, ctr.y, ctr.z, ctr.w};
    float dlv[4] = {dl.x, dl.y, dl.z, dl.w};
    float dtv[4] = {dt.x, dt.y, dt.z, dt.w};
    float drv[4] = {dr.x, dr.y, dr.z, dr.w};
    float dbv[4] = {db.x, db.y, db.z, db.w};
#pragma unroll
    for (int k = 0; k < 4; k++) {
        float s = sqrtf(sigmoidf_(mv[k]) * sigmoidf_(ctv[k]));
        if (!(s > THRESH_F)) s = 0.0f;
        float px = (float)(x + k) * (float)stride + 0.5f * (float)stride;
        float x1 = fminf(fmaxf(px - dlv[k], 0.0f), IMG_W_F);
        float y1 = fminf(fmaxf(py - dtv[k], 0.0f), IMG_H_F);
        float x2 = fminf(fmaxf(px + drv[k], 0.0f), IMG_W_F);
        float y2 = fminf(fmaxf(py + dbv[k], 0.0f), IMG_H_F);
        sc[k] = s; lab[k] = mic[k];
        box[k] = make_float4(x1, y1, x2, y2);
    }

    int base = n * NP + loc;
    *(float4*)&g_scores[base] = make_float4(sc[0], sc[1], sc[2], sc[3]);
    *(int4*)&g_labels[base]   = make_int4(lab[0], lab[1], lab[2], lab[3]);
    float4* bout = (float4*)&g_boxes[(size_t)base * 4];
    bout[0] = box[0]; bout[1] = box[1]; bout[2] = box[2]; bout[3] = box[3];
}

// ============ Kernel 2: fused top-K select + sort (per batch) ============
__global__ void __launch_bounds__(1024) k_topk() {
    __shared__ int hist[HBINS];                 // 16 KB
    __shared__ unsigned long long key[CAND];    // 16 KB
    __shared__ int wt[32];
    __shared__ int wsuf[32];
    __shared__ int sB, sCnt;

    int n = blockIdx.x;
    int tid = threadIdx.x;
    int lane = tid & 31;
    int warp = tid >> 5;
    const unsigned FULL = 0xFFFFFFFFu;

    for (int i = tid; i < HBINS; i += 1024) hist[i] = 0;
    __syncthreads();

    // pass A: linear histogram of scores (scores in [0,1))
    for (int p = tid; p < NP; p += 1024) {
        float s = g_scores[n * NP + p];
        int b = min((int)(s * (float)HBINS), HBINS - 1);
        atomicAdd(&hist[b], 1);
    }
    __syncthreads();

    // chunk sums: thread t owns bins [t*4, t*4+4)
    int b0 = tid * 4;
    int c = 0;
#pragma unroll
    for (int k = 0; k < 4; k++) c += hist[b0 + k];
    int x = c;
    for (int d = 1; d < 32; d <<= 1) {
        int y = __shfl_down_sync(FULL, x, d);
        if (lane + d < 32) x += y;
    }
    if (lane == 0) wt[warp] = x;
    __syncthreads();
    if (warp == 0) {
        int t = wt[lane];
        int xx = t;
        for (int d = 1; d < 32; d <<= 1) {
            int y = __shfl_down_sync(FULL, xx, d);
            if (lane + d < 32) xx += y;
        }
        wsuf[lane] = xx - t;
    }
    if (tid == 0) sCnt = 0;
    __syncthreads();

    int S = wsuf[warp] + (x - c);
    if (S < PRE_K && S + c >= PRE_K) {
        int acc = S;
        for (int k = 3; k >= 0; k--) {
            acc += hist[b0 + k];
            if (acc >= PRE_K) { sB = b0 + k; break; }
        }
    }
    __syncthreads();
    int B = sB;

    // pass B: collect candidates with bin >= B into smem keys
    for (int p = tid; p < NP; p += 1024) {
        float s = g_scores[n * NP + p];
        int b = min((int)(s * (float)HBINS), HBINS - 1);
        if (b >= B) {
            int pos = atomicAdd(&sCnt, 1);
            if (pos < CAND)
                key[pos] = ((unsigned long long)__float_as_uint(s) << 32)
                         | (unsigned)(~(unsigned)p);
        }
    }
    __syncthreads();
    int cnt = min(sCnt, CAND);
    for (int i = cnt + tid; i < CAND; i += 1024) key[i] = 0ull;
    __syncthreads();

    // bitonic sort desc, 2048 elements, 2 per thread
    for (int k = 2; k <= CAND; k <<= 1) {
        for (int j = k >> 1; j > 0; j >>= 1) {
#pragma unroll
            for (int e = 0; e < 2; e++) {
                int idx = tid + e * 1024;
                int ixj = idx ^ j;
                if (ixj > idx) {
                    unsigned long long a = key[idx], b2 = key[ixj];
                    bool desc = (idx & k) == 0;
                    if ((a < b2) == desc) { key[idx] = b2; key[ixj] = a; }
                }
            }
            __syncthreads();
        }
    }

    // output top-1000 + valid words
    unsigned long long kk = (tid < PRE_K) ? key[tid] : 0ull;
    float s = __uint_as_float((unsigned)(kk >> 32));
    unsigned bal = __ballot_sync(FULL, (tid < PRE_K) && (s > 0.0f));
    if (lane == 0) g_validw[n * 32 + warp] = bal;
    if (tid < PRE_K) {
        int src_idx = (int)(~(unsigned)(kk & 0xFFFFFFFFull));
        int d = n * PRE_K + tid;
        g_tscore[d] = s;
        g_tlabel[d] = g_labels[n * NP + src_idx];
        *(float4*)&g_tbox[(size_t)d * 4] =
            *(const float4*)&g_boxes[((size_t)n * NP + src_idx) * 4];
    }
}

// ============ Kernel 3: suppression mask (transposed layout, striped rows) ============
__global__ void k_mask() {
    __shared__ float4 sbox[1024];
    int n = blockIdx.x;
    int iblk = blockIdx.y;
    int tid = threadIdx.x;
    const unsigned FULL = 0xFFFFFFFFu;

    for (int i = tid; i < 1024; i += blockDim.x) {
        float4 b;
        if (i < PRE_K) {
            b = *(const float4*)&g_tbox[((size_t)n * PRE_K + i) * 4];
            float o = (float)g_tlabel[n * PRE_K + i] * CLS_OFF_F;
            b.x += o; b.y += o; b.z += o; b.w += o;
        } else {
            b = make_float4(0.f, 0.f, 0.f, 0.f);   // zero box -> iou = 0
        }
        sbox[i] = b;
    }
    __syncthreads();

    int w = tid >> 5;
    int lane = tid & 31;
    int j = w * 32 + lane;
    float4 jb = sbox[j];
    float ja = (jb.z - jb.x) * (jb.w - jb.y);

    int imax = w * 32 + 31;                  // rows i >= imax have no j>i in chunk
    int ilim = min(PRE_K, imax);
    int tmax = (ilim - iblk + 7) >> 3;       // i = iblk + 8t < ilim
    if (tmax < 0) tmax = 0;
    unsigned* mrow = &g_maskT[((size_t)n * 32 + w) * 1024];

#pragma unroll 2
    for (int t = 0; t < tmax; t++) {
        int i = iblk + t * 8;
        float4 ib = sbox[i];                 // broadcast, conflict-free
        float ia = (ib.z - ib.x) * (ib.w - ib.y);
        float xx1 = fmaxf(ib.x, jb.x);
        float yy1 = fmaxf(ib.y, jb.y);
        float xx2 = fminf(ib.z, jb.z);
        float yy2 = fminf(ib.w, jb.w);
        float iw = fmaxf(xx2 - xx1, 0.0f);
        float ih = fmaxf(yy2 - yy1, 0.0f);
        float inter = iw * ih;
        float iou = inter / (ia + ja - inter + 1e-9f);
        unsigned bal = __ballot_sync(FULL, iou > IOU_THR_F);
        if (lane == 0) {
            if ((i >> 5) == w) bal &= ~((2u << (i & 31)) - 1u);   // clear j <= i
            mrow[i] = bal;
        }
    }
}

// ============ Kernel 4: greedy sweep (vector tiles, double-buffered) ============
__device__ __forceinline__ void sweep_tile(int W, const uint4 (&cur)[8],
                                           unsigned& v, int lane) {
    const unsigned FULL = 0xFFFFFFFFu;
    unsigned vw = __shfl_sync(FULL, v, W);
    // within-word closure: only lane W's column (the diagonal) is meaningful;
    // all lanes compute redundantly, lane W's result is broadcast.
    unsigned alive = vw;
#pragma unroll
    for (int k = 0; k < 8; k++) {
        if ((alive >> (4 * k + 0)) & 1u) alive &= ~cur[k].x;
        if ((alive >> (4 * k + 1)) & 1u) alive &= ~cur[k].y;
        if ((alive >> (4 * k + 2)) & 1u) alive &= ~cur[k].z;
        if ((alive >> (4 * k + 3)) & 1u) alive &= ~cur[k].w;
    }
    alive = __shfl_sync(FULL, alive, W);
    if (lane == W) v = alive;
    // cross-word suppression: lane L's column = maskT[L][i] (zero for L<W)
#pragma unroll
    for (int k = 0; k < 8; k++) {
        if ((alive >> (4 * k + 0)) & 1u) v &= ~cur[k].x;
        if ((alive >> (4 * k + 1)) & 1u) v &= ~cur[k].y;
        if ((alive >> (4 * k + 2)) & 1u) v &= ~cur[k].z;
        if ((alive >> (4 * k + 3)) & 1u) v &= ~cur[k].w;
    }
}

__global__ void k_sweep(float* out) {
    __shared__ int s_sel [POST_K];
    __shared__ int s_kept[POST_K];

    int n = blockIdx.x;
    int tid = threadIdx.x;
    int lane = tid & 31;
    const unsigned FULL = 0xFFFFFFFFu;

    if (tid < 32) {
        unsigned v = g_validw[n * 32 + lane];
        const uint4* tb = (const uint4*)&g_maskT[((size_t)n * 32 + lane) * 1024];

        uint4 A[8], B[8];
#pragma unroll
        for (int k = 0; k < 8; k++) A[k] = tb[k];              // tile 0

#pragma unroll
        for (int h = 0; h < 16; h++) {
            int W0 = 2 * h, W1 = 2 * h + 1;
#pragma unroll
            for (int k = 0; k < 8; k++) B[k] = tb[W1 * 8 + k]; // prefetch odd tile
            sweep_tile(W0, A, v, lane);
            if (h < 15) {
#pragma unroll
                for (int k = 0; k < 8; k++) A[k] = tb[(W1 + 1) * 8 + k]; // prefetch next even
            }
            sweep_tile(W1, B, v, lane);
        }

        // stable partition (kept in index order, then dropped in index order)
        int c = __popc(v);
        int incl = c;
        for (int d = 1; d < 32; d <<= 1) {
            int t = __shfl_up_sync(FULL, incl, d);
            if (lane >= d) incl += t;
        }
        int pre = incl - c;
        int totK = __shfl_sync(FULL, incl, 31);
        for (int b = 0; b < 32; b++) {
            int i = lane * 32 + b;
            if (i >= PRE_K) break;
            bool kept = (v >> b) & 1u;
            int kb = pre + __popc(v & ((1u << b) - 1u));
            int pos = kept ? kb : (totK + (i - kb));
            if (pos < POST_K) { s_sel[pos] = i; s_kept[pos] = kept ? 1 : 0; }
        }
    }
    __syncthreads();

    if (tid < POST_K) {
        int i = s_sel[tid];
        int kept = s_kept[tid];
        int src = n * PRE_K + i;
        int dst = n * POST_K + tid;
        float4 b = *(const float4*)&g_tbox[(size_t)src * 4];
        ((float4*)out)[dst] = b;
        out[NB * POST_K * 4 + dst] = kept ? g_tscore[src] : 0.0f;          // scores
        out[NB * POST_K * 4 + NB * POST_K + dst] = (float)g_tlabel[src];   // labels
    }
}

// ---------------- host launch ----------------
extern "C" void kernel_launch(void* const* d_in, const int* in_sizes, int n_in,
                              void* d_out, int out_size) {
    (void)in_sizes; (void)n_in; (void)out_size;

    Ptrs p;
    for (int l = 0; l < 5; l++) {
        p.cls[l] = (const float*)d_in[3 * l + 0];
        p.reg[l] = (const float*)d_in[3 * l + 1];
        p.ctr[l] = (const float*)d_in[3 * l + 2];
    }
    float* out = (float*)d_out;

    int total = NB * NP4;
    k_decode<<<(total + 255) / 256, 256>>>(p);
    k_topk<<<NB, 1024>>>();
    k_mask<<<dim3(NB, 8), 1024>>>();
    k_sweep<<<NB, 128>>>(out);
}

// round 11
// speedup vs baseline: 6.5644x; 1.1886x over previous
#include <cuda_runtime.h>
#include <cuda_bf16.h>
#include <cstdint>

// ---------------- problem constants ----------------
#define NB 16        // batch
#define NC 80        // classes
#define NP 17064     // total locations across 5 levels
#define NP4 (NP / 4) // 4266
#define PRE_K 1000
#define POST_K 100
#define CAND 2048
#define HBINS 4096
#define IMG_W_F 1024.0f
#define IMG_H_F 800.0f
#define THRESH_F 0.05f
#define IOU_THR_F 0.6f
#define CLS_OFF_F 4096.0f

struct Ptrs {
    const float* cls[5];
    const float* reg[5];
    const float* ctr[5];
};

// ---------------- device scratch (static, no allocs; zero-initialized) ----------------
__device__ float    g_scores[NB * NP];
__device__ int      g_labels[NB * NP];
__device__ float    g_boxes [NB * NP * 4];
__device__ float    g_tscore[NB * PRE_K];
__device__ int      g_tlabel[NB * PRE_K];
__device__ float    g_tbox  [NB * PRE_K * 4];
// transposed mask: g_maskT[(n*32 + w) * 1024 + i] = suppression word of j-chunk w by box i.
// rows i in [ilim,1024) never written by any run -> stay zero (triangular invariant).
__device__ unsigned g_maskT [NB * 32 * 1024];
__device__ unsigned g_validw[NB * 32];

__device__ __forceinline__ float sigmoidf_(float x) {
    return 1.0f / (1.0f + expf(-x));
}

// ============ Kernel 1: decode, 4 consecutive locations per thread ============
__global__ void k_decode(Ptrs p) {
    int gid = blockIdx.x * blockDim.x + threadIdx.x;
    if (gid >= NB * NP4) return;
    int n = gid / NP4;
    int loc = (gid - n * NP4) * 4;

    int l, off, ww, stride, hw;
    if (loc < 12800)      { l = 0; off = 0;     ww = 128; stride = 8;   hw = 12800; }
    else if (loc < 16000) { l = 1; off = 12800; ww = 64;  stride = 16;  hw = 3200;  }
    else if (loc < 16800) { l = 2; off = 16000; ww = 32;  stride = 32;  hw = 800;   }
    else if (loc < 17008) { l = 3; off = 16800; ww = 16;  stride = 64;  hw = 208;   }
    else                  { l = 4; off = 17008; ww = 8;   stride = 128; hw = 56;    }

    int local = loc - off;               // multiple of 4; ww % 4 == 0 -> same row
    int y = local / ww;
    int x = local - y * ww;

    // argmax over class logits for 4 locations (sigmoid monotone)
    const float4* cls = (const float4*)(p.cls[l] + (size_t)n * NC * hw + local);
    size_t cstride = (size_t)hw / 4;     // float4 stride between classes
    float4 m = __ldg(&cls[0]);
    int mi0 = 0, mi1 = 0, mi2 = 0, mi3 = 0;
#pragma unroll 16
    for (int c = 1; c < NC; c++) {
        float4 v = __ldg(&cls[(size_t)c * cstride]);
        if (v.x > m.x) { m.x = v.x; mi0 = c; }
        if (v.y > m.y) { m.y = v.y; mi1 = c; }
        if (v.z > m.z) { m.z = v.z; mi2 = c; }
        if (v.w > m.w) { m.w = v.w; mi3 = c; }
    }

    float4 ctr = __ldg((const float4*)(p.ctr[l] + (size_t)n * hw + local));
    const float* reg = p.reg[l] + (size_t)n * 4 * hw + local;
    float4 dl = __ldg((const float4*)(reg));
    float4 dt = __ldg((const float4*)(reg + hw));
    float4 dr = __ldg((const float4*)(reg + 2 * hw));
    float4 db = __ldg((const float4*)(reg + 3 * hw));

    float py = (float)y * (float)stride + 0.5f * (float)stride;
    float sc[4]; int lab[4]; float4 box[4];
    float mv[4] = {m.x, m.y, m.z, m.w};
    int   mic[4] = {mi0, mi1, mi2, mi3};
    float ctv[4] = {ctr.x, ctr.y, ctr.z, ctr.w};
    float dlv[4] = {dl.x, dl.y, dl.z, dl.w};
    float dtv[4] = {dt.x, dt.y, dt.z, dt.w};
    float drv[4] = {dr.x, dr.y, dr.z, dr.w};
    float dbv[4] = {db.x, db.y, db.z, db.w};
#pragma unroll
    for (int k = 0; k < 4; k++) {
        float s = sqrtf(sigmoidf_(mv[k]) * sigmoidf_(ctv[k]));
        if (!(s > THRESH_F)) s = 0.0f;
        float px = (float)(x + k) * (float)stride + 0.5f * (float)stride;
        float x1 = fminf(fmaxf(px - dlv[k], 0.0f), IMG_W_F);
        float y1 = fminf(fmaxf(py - dtv[k], 0.0f), IMG_H_F);
        float x2 = fminf(fmaxf(px + drv[k], 0.0f), IMG_W_F);
        float y2 = fminf(fmaxf(py + dbv[k], 0.0f), IMG_H_F);
        sc[k] = s; lab[k] = mic[k];
        box[k] = make_float4(x1, y1, x2, y2);
    }

    int base = n * NP + loc;
    *(float4*)&g_scores[base] = make_float4(sc[0], sc[1], sc[2], sc[3]);
    *(int4*)&g_labels[base]   = make_int4(lab[0], lab[1], lab[2], lab[3]);
    float4* bout = (float4*)&g_boxes[(size_t)base * 4];
    bout[0] = box[0]; bout[1] = box[1]; bout[2] = box[2]; bout[3] = box[3];
}

// ============ Kernel 2: fused top-K select + sort (per batch) ============
__global__ void __launch_bounds__(1024) k_topk() {
    __shared__ int hist[HBINS];                 // 16 KB
    __shared__ unsigned long long key[CAND];    // 16 KB
    __shared__ int wt[32];
    __shared__ int wsuf[32];
    __shared__ int sB, sCnt;

    int n = blockIdx.x;
    int tid = threadIdx.x;
    int lane = tid & 31;
    int warp = tid >> 5;
    const unsigned FULL = 0xFFFFFFFFu;

    for (int i = tid; i < HBINS; i += 1024) hist[i] = 0;
    __syncthreads();

    // pass A: linear histogram of scores (scores in [0,1))
    for (int p = tid; p < NP; p += 1024) {
        float s = g_scores[n * NP + p];
        int b = min((int)(s * (float)HBINS), HBINS - 1);
        atomicAdd(&hist[b], 1);
    }
    __syncthreads();

    // chunk sums: thread t owns bins [t*4, t*4+4)
    int b0 = tid * 4;
    int c = 0;
#pragma unroll
    for (int k = 0; k < 4; k++) c += hist[b0 + k];
    int x = c;
    for (int d = 1; d < 32; d <<= 1) {
        int y = __shfl_down_sync(FULL, x, d);
        if (lane + d < 32) x += y;
    }
    if (lane == 0) wt[warp] = x;
    __syncthreads();
    if (warp == 0) {
        int t = wt[lane];
        int xx = t;
        for (int d = 1; d < 32; d <<= 1) {
            int y = __shfl_down_sync(FULL, xx, d);
            if (lane + d < 32) xx += y;
        }
        wsuf[lane] = xx - t;
    }
    if (tid == 0) sCnt = 0;
    __syncthreads();

    int S = wsuf[warp] + (x - c);
    if (S < PRE_K && S + c >= PRE_K) {
        int acc = S;
        for (int k = 3; k >= 0; k--) {
            acc += hist[b0 + k];
            if (acc >= PRE_K) { sB = b0 + k; break; }
        }
    }
    __syncthreads();
    int B = sB;

    // pass B: collect candidates with bin >= B into smem keys
    for (int p = tid; p < NP; p += 1024) {
        float s = g_scores[n * NP + p];
        int b = min((int)(s * (float)HBINS), HBINS - 1);
        if (b >= B) {
            int pos = atomicAdd(&sCnt, 1);
            if (pos < CAND)
                key[pos] = ((unsigned long long)__float_as_uint(s) << 32)
                         | (unsigned)(~(unsigned)p);
        }
    }
    __syncthreads();
    int cnt = min(sCnt, CAND);
    for (int i = cnt + tid; i < CAND; i += 1024) key[i] = 0ull;
    __syncthreads();

    // bitonic sort desc, 2048 elements, 2 per thread
    for (int k = 2; k <= CAND; k <<= 1) {
        for (int j = k >> 1; j > 0; j >>= 1) {
#pragma unroll
            for (int e = 0; e < 2; e++) {
                int idx = tid + e * 1024;
                int ixj = idx ^ j;
                if (ixj > idx) {
                    unsigned long long a = key[idx], b2 = key[ixj];
                    bool desc = (idx & k) == 0;
                    if ((a < b2) == desc) { key[idx] = b2; key[ixj] = a; }
                }
            }
            __syncthreads();
        }
    }

    // output top-1000 + valid words
    unsigned long long kk = (tid < PRE_K) ? key[tid] : 0ull;
    float s = __uint_as_float((unsigned)(kk >> 32));
    unsigned bal = __ballot_sync(FULL, (tid < PRE_K) && (s > 0.0f));
    if (lane == 0) g_validw[n * 32 + warp] = bal;
    if (tid < PRE_K) {
        int src_idx = (int)(~(unsigned)(kk & 0xFFFFFFFFull));
        int d = n * PRE_K + tid;
        g_tscore[d] = s;
        g_tlabel[d] = g_labels[n * NP + src_idx];
        *(float4*)&g_tbox[(size_t)d * 4] =
            *(const float4*)&g_boxes[((size_t)n * NP + src_idx) * 4];
    }
}

// ============ Kernel 3: suppression mask (transposed layout, striped rows) ============
__global__ void k_mask() {
    __shared__ float4 sbox[1024];
    int n = blockIdx.x;
    int iblk = blockIdx.y;
    int tid = threadIdx.x;
    const unsigned FULL = 0xFFFFFFFFu;

    for (int i = tid; i < 1024; i += blockDim.x) {
        float4 b;
        if (i < PRE_K) {
            b = *(const float4*)&g_tbox[((size_t)n * PRE_K + i) * 4];
            float o = (float)g_tlabel[n * PRE_K + i] * CLS_OFF_F;
            b.x += o; b.y += o; b.z += o; b.w += o;
        } else {
            b = make_float4(0.f, 0.f, 0.f, 0.f);   // zero box -> iou = 0
        }
        sbox[i] = b;
    }
    __syncthreads();

    int w = tid >> 5;
    int lane = tid & 31;
    int j = w * 32 + lane;
    float4 jb = sbox[j];
    float ja = (jb.z - jb.x) * (jb.w - jb.y);

    int imax = w * 32 + 31;                  // rows i >= imax have no j>i in chunk
    int ilim = min(PRE_K, imax);
    int tmax = (ilim - iblk + 7) >> 3;       // i = iblk + 8t < ilim
    if (tmax < 0) tmax = 0;
    unsigned* mrow = &g_maskT[((size_t)n * 32 + w) * 1024];

#pragma unroll 2
    for (int t = 0; t < tmax; t++) {
        int i = iblk + t * 8;
        float4 ib = sbox[i];                 // broadcast, conflict-free
        float ia = (ib.z - ib.x) * (ib.w - ib.y);
        float xx1 = fmaxf(ib.x, jb.x);
        float yy1 = fmaxf(ib.y, jb.y);
        float xx2 = fminf(ib.z, jb.z);
        float yy2 = fminf(ib.w, jb.w);
        float iw = fmaxf(xx2 - xx1, 0.0f);
        float ih = fmaxf(yy2 - yy1, 0.0f);
        float inter = iw * ih;
        float iou = inter / (ia + ja - inter + 1e-9f);
        unsigned bal = __ballot_sync(FULL, iou > IOU_THR_F);
        if (lane == 0) {
            if ((i >> 5) == w) bal &= ~((2u << (i & 31)) - 1u);   // clear j <= i
            mrow[i] = bal;
        }
    }
}

// ============ Kernel 4: greedy sweep (smem-staged tiles, 32-warp producers) ============
// buf[ph][L][pitch 129]: phase = 4 tiles = 128 words per row L.
// Thread (warp w, lane L): loads uint4 = g_maskT row L, words ph*128 + w*4.
__global__ void __launch_bounds__(1024) k_sweep(float* out) {
    __shared__ unsigned buf[2][32][129];    // 33 KB
    __shared__ int s_sel [POST_K];
    __shared__ int s_kept[POST_K];

    int n = blockIdx.x;
    int tid = threadIdx.x;
    int lane = tid & 31;
    int warp = tid >> 5;
    const unsigned FULL = 0xFFFFFFFFu;

    const uint4* gp = (const uint4*)&g_maskT[((size_t)n * 32 + lane) * 1024];
    // prologue: stage phase 0
    uint4 mine = gp[warp];                  // ph=0: uint4 index warp
    {
        unsigned* d = &buf[0][lane][warp * 4];
        d[0] = mine.x; d[1] = mine.y; d[2] = mine.z; d[3] = mine.w;
    }
    __syncthreads();

    unsigned v = (tid < 32) ? g_validw[n * 32 + lane] : 0u;

#pragma unroll 1
    for (int ph = 0; ph < 8; ph++) {
        // issue next-phase loads early (latency covered by warp-0 compute)
        if (ph < 7) mine = gp[(ph + 1) * 32 + warp];

        if (tid < 32) {
            const unsigned (&tile)[32][129] = *(const unsigned (*)[32][129])&buf[ph & 1];
#pragma unroll
            for (int t = 0; t < 4; t++) {
                int W = ph * 4 + t;
                unsigned vw = __shfl_sync(FULL, v, W);
                if (vw == 0) continue;      // warp-uniform skip
                int cbase = t * 32;
                // within-word closure: lane W's column is the diagonal word
                unsigned alive = vw;
#pragma unroll
                for (int b = 0; b < 32; b++) {
                    unsigned r = tile[lane][cbase + b];
                    if ((alive >> b) & 1u) alive &= ~r;
                }
                alive = __shfl_sync(FULL, alive, W);
                if (lane == W) v = alive;
                // cross-word suppression (lanes < W hold zero words; lane W idempotent)
#pragma unroll
                for (int b = 0; b < 32; b++) {
                    unsigned r = tile[lane][cbase + b];
                    if ((alive >> b) & 1u) v &= ~r;
                }
            }
        }
        __syncthreads();                     // compute(ph) done before overwrite
        if (ph < 7) {
            unsigned* d = &buf[(ph + 1) & 1][lane][warp * 4];
            d[0] = mine.x; d[1] = mine.y; d[2] = mine.z; d[3] = mine.w;
        }
        __syncthreads();                     // stage(ph+1) visible before compute
    }

    if (tid < 32) {
        // stable partition (kept in index order, then dropped in index order)
        int c = __popc(v);
        int incl = c;
        for (int d = 1; d < 32; d <<= 1) {
            int t = __shfl_up_sync(FULL, incl, d);
            if (lane >= d) incl += t;
        }
        int pre = incl - c;
        int totK = __shfl_sync(FULL, incl, 31);
        for (int b = 0; b < 32; b++) {
            int i = lane * 32 + b;
            if (i >= PRE_K) break;
            bool kept = (v >> b) & 1u;
            int kb = pre + __popc(v & ((1u << b) - 1u));
            int pos = kept ? kb : (totK + (i - kb));
            if (pos < POST_K) { s_sel[pos] = i; s_kept[pos] = kept ? 1 : 0; }
        }
    }
    __syncthreads();

    if (tid < POST_K) {
        int i = s_sel[tid];
        int kept = s_kept[tid];
        int src = n * PRE_K + i;
        int dst = n * POST_K + tid;
        float4 b = *(const float4*)&g_tbox[(size_t)src * 4];
        ((float4*)out)[dst] = b;
        out[NB * POST_K * 4 + dst] = kept ? g_tscore[src] : 0.0f;          // scores
        out[NB * POST_K * 4 + NB * POST_K + dst] = (float)g_tlabel[src];   // labels
    }
}

// ---------------- host launch ----------------
extern "C" void kernel_launch(void* const* d_in, const int* in_sizes, int n_in,
                              void* d_out, int out_size) {
    (void)in_sizes; (void)n_in; (void)out_size;

    Ptrs p;
    for (int l = 0; l < 5; l++) {
        p.cls[l] = (const float*)d_in[3 * l + 0];
        p.reg[l] = (const float*)d_in[3 * l + 1];
        p.ctr[l] = (const float*)d_in[3 * l + 2];
    }
    float* out = (float*)d_out;

    int total = NB * NP4;
    k_decode<<<(total + 255) / 256, 256>>>(p);
    k_topk<<<NB, 1024>>>();
    k_mask<<<dim3(NB, 8), 1024>>>();
    k_sweep<<<NB, 1024>>>(out);
}